// round 8
// baseline (speedup 1.0000x reference)
#include <cuda_runtime.h>

#define NBLOCKS 128
typedef unsigned long long ull;

__device__ __align__(16) float g_x  [1024*256];
__device__ __align__(16) float g_io [1024*768];    // shift|scale|proj_x
__device__ __align__(16) float g_p  [1024*2048];
__device__ __align__(16) float g_h  [1024*256];
__device__ __align__(16) float g_wpR [256*2048];   // Wp, tf32-rounded, [k][n]
__device__ __align__(16) float g_winR[256*768];    // Win, tf32-rounded, [k][n]
__device__ __align__(16) float g_woT [256*256];    // Wout transposed [n][k], full fp32
__device__ int g_len[16];
__device__ unsigned g_cnt = 0, g_gen = 0;
__device__ unsigned g_gcnt[16*32];                 // per-group barrier (128B padded)
__device__ unsigned g_ggen[16*32];

// ---------- helpers ----------
__device__ __forceinline__ ull pack2(float v){
    ull r; asm("mov.b64 %0, {%1, %1};" : "=l"(r) : "f"(v)); return r;
}
__device__ __forceinline__ ull packxy(float x, float y){
    ull r; asm("mov.b64 %0, {%1, %2};" : "=l"(r) : "f"(x), "f"(y)); return r;
}
__device__ __forceinline__ float2 unpack2(ull v){
    float2 r; asm("mov.b64 {%0, %1}, %2;" : "=f"(r.x), "=f"(r.y) : "l"(v)); return r;
}
__device__ __forceinline__ void ffma2(ull& d, ull a, ull b){
    asm("fma.rn.f32x2 %0, %1, %2, %0;" : "+l"(d) : "l"(a), "l"(b));
}
__device__ __forceinline__ void cpa16(void* s, const void* g){
    unsigned ss = (unsigned)__cvta_generic_to_shared(s);
    asm volatile("cp.async.cg.shared.global [%0], [%1], 16;\n" :: "r"(ss), "l"(g));
}
#define CPA_COMMIT() asm volatile("cp.async.commit_group;\n" ::: "memory")
#define CPA_WAIT0()  asm volatile("cp.async.wait_group 0;\n" ::: "memory")

__device__ __forceinline__ float to_tf32(float x){
    float r; asm("cvt.rna.tf32.f32 %0, %1;" : "=f"(r) : "f"(x)); return r;
}

// legacy HMMA m16n8k8 tf32 (base sm_103-legal)
__device__ __forceinline__ void mma_tf32(float* d, const unsigned* a, const unsigned* b){
    asm volatile(
        "mma.sync.aligned.m16n8k8.row.col.f32.tf32.tf32.f32 "
        "{%0,%1,%2,%3}, {%4,%5,%6,%7}, {%8,%9}, {%0,%1,%2,%3};"
        : "+f"(d[0]), "+f"(d[1]), "+f"(d[2]), "+f"(d[3])
        : "r"(a[0]), "r"(a[1]), "r"(a[2]), "r"(a[3]), "r"(b[0]), "r"(b[1]));
}

// ---------- dynamic smem ----------
#define SMEM_DYN 87040
struct Step2Sm { float ls[4][8][256]; float hsm[256][12]; };

// ---------- barriers ----------
__device__ __forceinline__ void grid_sync(){
    __threadfence();
    __syncthreads();
    if (threadIdx.x == 0){
        unsigned my = *(volatile unsigned*)&g_gen;
        if (atomicAdd(&g_cnt, 1u) == NBLOCKS - 1u){
            g_cnt = 0;
            __threadfence();
            atomicAdd(&g_gen, 1u);
        } else {
            while (*(volatile unsigned*)&g_gen == my) __nanosleep(64);
        }
        __threadfence();
    }
    __syncthreads();
}

// 8-block group barrier: group b = blocks 8b..8b+7 (one batch)
__device__ __forceinline__ void group_sync(int b){
    __threadfence();
    __syncthreads();
    if (threadIdx.x == 0){
        volatile unsigned* gen = &g_ggen[b*32];
        unsigned my = *gen;
        if (atomicAdd(&g_gcnt[b*32], 1u) == 7u){
            g_gcnt[b*32] = 0;
            __threadfence();
            atomicAdd((unsigned*)&g_ggen[b*32], 1u);
        } else {
            while (*gen == my) __nanosleep(32);
        }
        __threadfence();     // acquire: CCTL.IVALL flushes this SM's L1D
    }
    __syncthreads();
}

// ---------- HMMA GEMM tile: 64(m) x 256(n), K=256 ----------
// 16 warps as 2m x 8n; warp tile 32x32 (2 m16-groups x 4 n8-frags)
__device__ void gemm_mma(const float* __restrict__ Asrc, const float* __restrict__ Bsrc,
                         const float* __restrict__ bias, float* __restrict__ outp,
                         int N, int m0, int n0, bool do_ln, char* dyn,
                         float (*s_red)[8][2])
{
    const int t = threadIdx.x, w = t >> 5, lane = t & 31;
    const int wm = w & 1, wn = w >> 1;
    const int r4 = lane >> 2, q = lane & 3;

    float* Asm = (float*)dyn;              // [2][64*36]
    float* Bsm = (float*)(dyn + 18432);    // [2][32*264]

    float acc[2][4][4];
    #pragma unroll
    for (int g = 0; g < 2; g++)
        #pragma unroll
        for (int f = 0; f < 4; f++)
            #pragma unroll
            for (int rr = 0; rr < 4; rr++) acc[g][f][rr] = 0.f;

    const int am = t >> 3, ak4 = (t & 7) * 4;

    cpa16(Asm + am*36 + ak4, Asrc + (size_t)(m0 + am)*256 + ak4);
    #pragma unroll
    for (int i = 0; i < 4; i++){
        int e = t + i*512, k = e >> 6, n4 = (e & 63) * 4;
        cpa16(Bsm + k*264 + n4, Bsrc + (size_t)k*N + n0 + n4);
    }
    CPA_COMMIT(); CPA_WAIT0();
    __syncthreads();

    for (int c = 0; c < 8; c++){
        const int buf = c & 1;
        if (c < 7){
            const int nb = buf ^ 1;
            cpa16(Asm + nb*2304 + am*36 + ak4,
                  Asrc + (size_t)(m0 + am)*256 + (c+1)*32 + ak4);
            #pragma unroll
            for (int i = 0; i < 4; i++){
                int e = t + i*512, k = e >> 6, n4 = (e & 63) * 4;
                cpa16(Bsm + nb*8448 + k*264 + n4,
                      Bsrc + (size_t)((c+1)*32 + k)*N + n0 + n4);
            }
            CPA_COMMIT();
        }
        const float* Ab = Asm + buf*2304 + (wm*32 + r4)*36 + q;
        const float* Bb = Bsm + buf*8448 + q*264 + wn*32 + r4;
        #pragma unroll
        for (int ks = 0; ks < 4; ks++){
            unsigned a[2][4], b[4][2];
            const float* Ak = Ab + ks*8;
            #pragma unroll
            for (int g = 0; g < 2; g++){
                const float* Ag = Ak + g*16*36;
                a[g][0] = __float_as_uint(Ag[0]);
                a[g][1] = __float_as_uint(Ag[8*36]);
                a[g][2] = __float_as_uint(Ag[4]);
                a[g][3] = __float_as_uint(Ag[8*36 + 4]);
            }
            const float* Bk = Bb + ks*8*264;
            #pragma unroll
            for (int f = 0; f < 4; f++){
                b[f][0] = __float_as_uint(Bk[f*8]);
                b[f][1] = __float_as_uint(Bk[4*264 + f*8]);
            }
            #pragma unroll
            for (int g = 0; g < 2; g++)
                #pragma unroll
                for (int f = 0; f < 4; f++)
                    mma_tf32(acc[g][f], a[g], b[f]);
        }
        if (c < 7) CPA_WAIT0();
        __syncthreads();
    }

    #pragma unroll
    for (int f = 0; f < 4; f++){
        float b0 = bias[n0 + wn*32 + f*8 + 2*q];
        float b1 = bias[n0 + wn*32 + f*8 + 2*q + 1];
        #pragma unroll
        for (int g = 0; g < 2; g++){
            acc[g][f][0] += b0; acc[g][f][1] += b1;
            acc[g][f][2] += b0; acc[g][f][3] += b1;
        }
    }

    if (do_ln){
        #pragma unroll
        for (int g = 0; g < 2; g++)
            #pragma unroll
            for (int h = 0; h < 2; h++){
                float s1 = 0.f, s2 = 0.f;
                #pragma unroll
                for (int f = 0; f < 4; f++){
                    float v0 = acc[g][f][2*h], v1 = acc[g][f][2*h + 1];
                    s1 += v0 + v1; s2 += v0*v0 + v1*v1;
                }
                s1 += __shfl_xor_sync(0xffffffffu, s1, 1);
                s2 += __shfl_xor_sync(0xffffffffu, s2, 1);
                s1 += __shfl_xor_sync(0xffffffffu, s1, 2);
                s2 += __shfl_xor_sync(0xffffffffu, s2, 2);
                if (q == 0){
                    int rl = wm*32 + g*16 + h*8 + r4;
                    s_red[rl][wn][0] = s1; s_red[rl][wn][1] = s2;
                }
            }
        __syncthreads();
        #pragma unroll
        for (int g = 0; g < 2; g++)
            #pragma unroll
            for (int h = 0; h < 2; h++){
                int rl = wm*32 + g*16 + h*8 + r4;
                float t1 = 0.f, t2 = 0.f;
                #pragma unroll
                for (int j = 0; j < 8; j++){ t1 += s_red[rl][j][0]; t2 += s_red[rl][j][1]; }
                float mean = t1 * (1.f/256.f);
                float var  = t2 * (1.f/256.f) - mean*mean;
                float rstd = rsqrtf(var + 1e-5f);
                #pragma unroll
                for (int f = 0; f < 4; f++){
                    acc[g][f][2*h]   = (acc[g][f][2*h]   - mean) * rstd;
                    acc[g][f][2*h+1] = (acc[g][f][2*h+1] - mean) * rstd;
                }
            }
    }

    #pragma unroll
    for (int g = 0; g < 2; g++)
        #pragma unroll
        for (int h = 0; h < 2; h++){
            int row = m0 + wm*32 + g*16 + h*8 + r4;
            float* op = outp + (size_t)row*N + n0 + wn*32 + 2*q;
            #pragma unroll
            for (int f = 0; f < 4; f++){
                float2 o2; o2.x = acc[g][f][2*h]; o2.y = acc[g][f][2*h+1];
                *(float2*)(op + f*8) = o2;
            }
        }
    __syncthreads();
}

// ---------- step phase (FFMA2): block=(b, 8 j), 512 threads ----------
__device__ void step_phase(const float* __restrict__ A,
                           const float* __restrict__ bout, int iter, char* dyn)
{
    ull (*As)[8] = (ull(*)[8])dyn;
    Step2Sm* p2  = (Step2Sm*)dyn;

    const int t  = threadIdx.x;
    const int b  = blockIdx.x >> 3;
    const int j0 = (blockIdx.x & 7) * 8;
    const int row0 = b*64 + j0;

    const float* Ab = A + b*32768 + j0*8;
    #pragma unroll
    for (int idx = 0; idx < 4; idx++){
        int e = idx*512 + t;
        int kp = e >> 3, jj = e & 7;
        int k0 = kp*2;
        int base = (k0 >> 3)*512 + jj*8 + (k0 & 7);
        As[kp][jj] = packxy(Ab[base], Ab[base + 1]);
    }
    __syncthreads();

    const int tx = t & 127;
    const int ty = t >> 7;
    ull acc[8][2];
    #pragma unroll
    for (int jj = 0; jj < 8; jj++){ acc[jj][0] = 0ull; acc[jj][1] = 0ull; }

    const float* pb = g_p + (size_t)(b*64 + ty*16)*2048 + tx;
    #pragma unroll 2
    for (int ii = 0; ii < 16; ii++){
        const float* pr = pb + ii*2048;
        #pragma unroll
        for (int hp = 0; hp < 4; hp++){
            ull p0 = packxy(pr[hp*512],       pr[hp*512 + 256]);
            ull p1 = packxy(pr[hp*512 + 128], pr[hp*512 + 384]);
            const int kp = (ty*16 + ii)*4 + hp;
            ulonglong2 A01 = *(const ulonglong2*)&As[kp][0];
            ulonglong2 A23 = *(const ulonglong2*)&As[kp][2];
            ulonglong2 A45 = *(const ulonglong2*)&As[kp][4];
            ulonglong2 A67 = *(const ulonglong2*)&As[kp][6];
            ffma2(acc[0][0], A01.x, p0); ffma2(acc[0][1], A01.x, p1);
            ffma2(acc[1][0], A01.y, p0); ffma2(acc[1][1], A01.y, p1);
            ffma2(acc[2][0], A23.x, p0); ffma2(acc[2][1], A23.x, p1);
            ffma2(acc[3][0], A23.y, p0); ffma2(acc[3][1], A23.y, p1);
            ffma2(acc[4][0], A45.x, p0); ffma2(acc[4][1], A45.x, p1);
            ffma2(acc[5][0], A45.y, p0); ffma2(acc[5][1], A45.y, p1);
            ffma2(acc[6][0], A67.x, p0); ffma2(acc[6][1], A67.x, p1);
            ffma2(acc[7][0], A67.y, p0); ffma2(acc[7][1], A67.y, p1);
        }
    }
    __syncthreads();
    #pragma unroll
    for (int jj = 0; jj < 8; jj++){
        float2 u0 = unpack2(acc[jj][0]);
        float2 u1 = unpack2(acc[jj][1]);
        p2->ls[ty][jj][tx]       = u0.x + u0.y;
        p2->ls[ty][jj][tx + 128] = u1.x + u1.y;
    }
    __syncthreads();

    const int w = t >> 5, lane = t & 31;
    if (w < 8){
        const int r = w;
        const float* iorow = g_io + (size_t)(row0 + r)*768;
        float hv2[8];
        float s = 0.f;
        #pragma unroll
        for (int qq = 0; qq < 8; qq++){
            int d = qq*32 + lane;
            float x = p2->ls[0][r][d] + p2->ls[1][r][d]
                    + p2->ls[2][r][d] + p2->ls[3][r][d];
            x = x - tanhf(x);
            x += iorow[512 + d];
            hv2[qq] = x;
            s += x;
        }
        #pragma unroll
        for (int o = 16; o > 0; o >>= 1) s += __shfl_xor_sync(0xffffffffu, s, o);
        float mean = s * (1.f/256.f);
        float qv = 0.f;
        #pragma unroll
        for (int qq = 0; qq < 8; qq++){ float d = hv2[qq]-mean; qv += d*d; }
        #pragma unroll
        for (int o = 16; o > 0; o >>= 1) qv += __shfl_xor_sync(0xffffffffu, qv, o);
        float rr = rsqrtf(qv * (1.f/256.f) + 1e-5f);
        #pragma unroll
        for (int qq = 0; qq < 8; qq++){
            int d = qq*32 + lane;
            float lnv = (hv2[qq]-mean)*rr;
            float g = fmaf(iorow[d], lnv, iorow[256+d]);
            p2->hsm[d][r] = fmaxf(g, 0.f);
        }
    }
    __syncthreads();

    // phase 3: y = tanh(h @ Wout + b); Wout read transposed as float4
    const int n  = t & 255;
    const int g2 = t >> 8;
    ull yacc[2] = {0ull, 0ull};
    const float* wrow = g_woT + (size_t)n*256;
    #pragma unroll 4
    for (int k4 = 0; k4 < 64; k4++){
        float4 wv = *(const float4*)(wrow + k4*4);
        const int k = k4*4;
        { ull w2 = pack2(wv.x); ulonglong2 h2 = *(const ulonglong2*)&p2->hsm[k  ][g2*4]; ffma2(yacc[0], h2.x, w2); ffma2(yacc[1], h2.y, w2); }
        { ull w2 = pack2(wv.y); ulonglong2 h2 = *(const ulonglong2*)&p2->hsm[k+1][g2*4]; ffma2(yacc[0], h2.x, w2); ffma2(yacc[1], h2.y, w2); }
        { ull w2 = pack2(wv.z); ulonglong2 h2 = *(const ulonglong2*)&p2->hsm[k+2][g2*4]; ffma2(yacc[0], h2.x, w2); ffma2(yacc[1], h2.y, w2); }
        { ull w2 = pack2(wv.w); ulonglong2 h2 = *(const ulonglong2*)&p2->hsm[k+3][g2*4]; ffma2(yacc[0], h2.x, w2); ffma2(yacc[1], h2.y, w2); }
    }
    float bo = bout[n];
    bool masked = (iter > g_len[b]);
    float2 u0 = unpack2(yacc[0]);
    float2 u1 = unpack2(yacc[1]);
    g_h[(size_t)(row0 + 4*g2 + 0)*256 + n] = masked ? 0.f : to_tf32(tanhf(u0.x + bo));
    g_h[(size_t)(row0 + 4*g2 + 1)*256 + n] = masked ? 0.f : to_tf32(tanhf(u0.y + bo));
    g_h[(size_t)(row0 + 4*g2 + 2)*256 + n] = masked ? 0.f : to_tf32(tanhf(u1.x + bo));
    g_h[(size_t)(row0 + 4*g2 + 3)*256 + n] = masked ? 0.f : to_tf32(tanhf(u1.y + bo));
}

// ---------- single persistent kernel ----------
__global__ void __launch_bounds__(512) fused_kernel(
    const int* __restrict__ tokens, const float* __restrict__ A,
    const float* __restrict__ root, const float* __restrict__ emb,
    const float* __restrict__ Wp,   const float* __restrict__ bp,
    const float* __restrict__ Win,  const float* __restrict__ bin,
    const float* __restrict__ Wout, const float* __restrict__ bout,
    float* __restrict__ out)
{
    extern __shared__ char smraw[];
    char* dyn = (char*)((((size_t)smraw) + 1023) & ~(size_t)1023);
    __shared__ float s_red[64][8][2];

    const int bid = blockIdx.x;
    const int t = threadIdx.x;
    const int b = bid >> 3, r = bid & 7;

    // prologue
    {
        // group-local: gather batch b embeddings (tf32), zero h
        int idx = r*512 + t;                 // 0..4095: batch b has 4096 float4
        int l = idx >> 6;
        int c4 = (idx & 63) * 4;
        int row = b*64 + l;
        int tok = tokens[l*16 + b];
        float4 e4 = *(const float4*)&emb[(size_t)tok*256 + c4];
        e4.x = to_tf32(e4.x); e4.y = to_tf32(e4.y); e4.z = to_tf32(e4.z); e4.w = to_tf32(e4.w);
        *(float4*)&g_x[(size_t)row*256 + c4] = e4;
        float4 z; z.x=z.y=z.z=z.w=0.f;
        *(float4*)&g_h[(size_t)row*256 + c4] = z;
        if (r == 0 && t == 0){
            int c = 0;
            for (int l2 = 0; l2 < 64; l2++) c += (tokens[l2*16 + b] != 0);
            g_len[b] = c;
        }
        // global: tf32-rounded weight copies + Wout transpose
        int gidx = bid*512 + t;              // 0..65535
        #pragma unroll
        for (int i = 0; i < 2; i++){         // WpR: 131072 float4
            int e = gidx + i*65536;
            float4 v = *(const float4*)&Wp[(size_t)e*4];
            v.x = to_tf32(v.x); v.y = to_tf32(v.y); v.z = to_tf32(v.z); v.w = to_tf32(v.w);
            *(float4*)&g_wpR[(size_t)e*4] = v;
        }
        if (gidx < 49152){                   // WinR
            float4 v = *(const float4*)&Win[(size_t)gidx*4];
            v.x = to_tf32(v.x); v.y = to_tf32(v.y); v.z = to_tf32(v.z); v.w = to_tf32(v.w);
            *(float4*)&g_winR[(size_t)gidx*4] = v;
        }
        g_woT[gidx] = Wout[(size_t)(gidx & 255)*256 + (gidx >> 8)];   // [n][k]
    }
    grid_sync();   // ONE global sync: weights visible to all groups

    // hoisted in_proj (group-local: blocks r<3 cover N=768)
    if (r < 3)
        gemm_mma(g_x, g_winR, bin, g_io, 768, b*64, r*256, false, dyn, s_red);
    group_sync(b);

    // 64-step recurrence — fully batch-local from here on
    for (int it = 0; it < 64; it++){
        gemm_mma(g_h, g_wpR, bp, g_p, 2048, b*64, r*256, true, dyn, s_red);
        group_sync(b);
        step_phase(A, bout, 64 - it, dyn);
        group_sync(b);
    }

    // epilogue: out[b][d] = sum_i h[b,i,d] * root[b,i]
    if (r == 0 && t < 256){
        float s = 0.f;
        #pragma unroll 8
        for (int i = 0; i < 64; i++)
            s += g_h[(size_t)(b*64 + i)*256 + t] * root[b*64 + i];
        out[b*256 + t] = s;
    }
}

extern "C" void kernel_launch(void* const* d_in, const int* in_sizes, int n_in,
                              void* d_out, int out_size)
{
    const int*   tokens = (const int*)  d_in[0];
    const float* A      = (const float*)d_in[1];
    const float* root   = (const float*)d_in[2];
    const float* emb    = (const float*)d_in[3];
    const float* Wp     = (const float*)d_in[4];
    const float* bp     = (const float*)d_in[5];
    const float* Win    = (const float*)d_in[6];
    const float* bin    = (const float*)d_in[7];
    const float* Wout   = (const float*)d_in[8];
    const float* bout   = (const float*)d_in[9];

    cudaFuncSetAttribute(fused_kernel, cudaFuncAttributeMaxDynamicSharedMemorySize, SMEM_DYN);
    fused_kernel<<<NBLOCKS, 512, SMEM_DYN>>>(tokens, A, root, emb, Wp, bp, Win, bin,
                                             Wout, bout, (float*)d_out);
}

// round 9
// speedup vs baseline: 1.3641x; 1.3641x over previous
#include <cuda_runtime.h>

#define NBLOCKS 128
typedef unsigned long long ull;

__device__ __align__(16) float g_x  [1024*256];
__device__ __align__(16) float g_io [1024*768];    // shift|scale|proj_x
__device__ __align__(16) float g_p  [1024*2048];
__device__ __align__(16) float g_h  [1024*256];
__device__ __align__(16) float g_wpR [256*2048];   // Wp, tf32-rounded, [k][n]
__device__ __align__(16) float g_winR[256*768];    // Win, tf32-rounded, [k][n]
__device__ int g_len[16];
__device__ unsigned g_cnt = 0, g_gen = 0;
__device__ unsigned g_gcnt[16*32];                 // per-group barrier (128B padded)
__device__ unsigned g_ggen[16*32];

// ---------- helpers ----------
__device__ __forceinline__ ull pack2(float v){
    ull r; asm("mov.b64 %0, {%1, %1};" : "=l"(r) : "f"(v)); return r;
}
__device__ __forceinline__ ull packxy(float x, float y){
    ull r; asm("mov.b64 %0, {%1, %2};" : "=l"(r) : "f"(x), "f"(y)); return r;
}
__device__ __forceinline__ float2 unpack2(ull v){
    float2 r; asm("mov.b64 {%0, %1}, %2;" : "=f"(r.x), "=f"(r.y) : "l"(v)); return r;
}
__device__ __forceinline__ void ffma2(ull& d, ull a, ull b){
    asm("fma.rn.f32x2 %0, %1, %2, %0;" : "+l"(d) : "l"(a), "l"(b));
}
__device__ __forceinline__ void cpa16(void* s, const void* g){
    unsigned ss = (unsigned)__cvta_generic_to_shared(s);
    asm volatile("cp.async.cg.shared.global [%0], [%1], 16;\n" :: "r"(ss), "l"(g));
}
#define CPA_COMMIT() asm volatile("cp.async.commit_group;\n" ::: "memory")
#define CPA_WAIT0()  asm volatile("cp.async.wait_group 0;\n" ::: "memory")

__device__ __forceinline__ float to_tf32(float x){
    float r; asm("cvt.rna.tf32.f32 %0, %1;" : "=f"(r) : "f"(x)); return r;
}

// legacy HMMA m16n8k8 tf32 (base sm_103-legal)
__device__ __forceinline__ void mma_tf32(float* d, const unsigned* a, const unsigned* b){
    asm volatile(
        "mma.sync.aligned.m16n8k8.row.col.f32.tf32.tf32.f32 "
        "{%0,%1,%2,%3}, {%4,%5,%6,%7}, {%8,%9}, {%0,%1,%2,%3};"
        : "+f"(d[0]), "+f"(d[1]), "+f"(d[2]), "+f"(d[3])
        : "r"(a[0]), "r"(a[1]), "r"(a[2]), "r"(a[3]), "r"(b[0]), "r"(b[1]));
}

// ---------- dynamic smem ----------
#define SMEM_DYN 87040
struct Step2Sm { float ls[4][8][256]; float hsm[256][12]; };

// ---------- barriers ----------
__device__ __forceinline__ void grid_sync(){
    __threadfence();
    __syncthreads();
    if (threadIdx.x == 0){
        unsigned my = *(volatile unsigned*)&g_gen;
        if (atomicAdd(&g_cnt, 1u) == NBLOCKS - 1u){
            g_cnt = 0;
            __threadfence();
            atomicAdd(&g_gen, 1u);
        } else {
            while (*(volatile unsigned*)&g_gen == my) __nanosleep(64);
        }
        __threadfence();
    }
    __syncthreads();
}

// 8-block group barrier: group b = blocks 8b..8b+7 (one batch)
__device__ __forceinline__ void group_sync(int b){
    __threadfence();
    __syncthreads();
    if (threadIdx.x == 0){
        volatile unsigned* gen = &g_ggen[b*32];
        unsigned my = *gen;
        if (atomicAdd(&g_gcnt[b*32], 1u) == 7u){
            g_gcnt[b*32] = 0;
            __threadfence();
            atomicAdd((unsigned*)&g_ggen[b*32], 1u);
        } else {
            while (*gen == my) __nanosleep(32);
        }
        __threadfence();
    }
    __syncthreads();
}

// ---------- HMMA GEMM tile: 64(m) x 256(n), K=256 ----------
__device__ void gemm_mma(const float* __restrict__ Asrc, const float* __restrict__ Bsrc,
                         const float* __restrict__ bias, float* __restrict__ outp,
                         int N, int m0, int n0, bool do_ln, char* dyn,
                         float (*s_red)[8][2])
{
    const int t = threadIdx.x, w = t >> 5, lane = t & 31;
    const int wm = w & 1, wn = w >> 1;
    const int r4 = lane >> 2, q = lane & 3;

    float* Asm = (float*)dyn;              // [2][64*36]
    float* Bsm = (float*)(dyn + 18432);    // [2][32*264]

    float acc[2][4][4];
    #pragma unroll
    for (int g = 0; g < 2; g++)
        #pragma unroll
        for (int f = 0; f < 4; f++)
            #pragma unroll
            for (int rr = 0; rr < 4; rr++) acc[g][f][rr] = 0.f;

    const int am = t >> 3, ak4 = (t & 7) * 4;

    cpa16(Asm + am*36 + ak4, Asrc + (size_t)(m0 + am)*256 + ak4);
    #pragma unroll
    for (int i = 0; i < 4; i++){
        int e = t + i*512, k = e >> 6, n4 = (e & 63) * 4;
        cpa16(Bsm + k*264 + n4, Bsrc + (size_t)k*N + n0 + n4);
    }
    CPA_COMMIT(); CPA_WAIT0();
    __syncthreads();

    for (int c = 0; c < 8; c++){
        const int buf = c & 1;
        if (c < 7){
            const int nb = buf ^ 1;
            cpa16(Asm + nb*2304 + am*36 + ak4,
                  Asrc + (size_t)(m0 + am)*256 + (c+1)*32 + ak4);
            #pragma unroll
            for (int i = 0; i < 4; i++){
                int e = t + i*512, k = e >> 6, n4 = (e & 63) * 4;
                cpa16(Bsm + nb*8448 + k*264 + n4,
                      Bsrc + (size_t)((c+1)*32 + k)*N + n0 + n4);
            }
            CPA_COMMIT();
        }
        const float* Ab = Asm + buf*2304 + (wm*32 + r4)*36 + q;
        const float* Bb = Bsm + buf*8448 + q*264 + wn*32 + r4;
        #pragma unroll
        for (int ks = 0; ks < 4; ks++){
            unsigned a[2][4], b[4][2];
            const float* Ak = Ab + ks*8;
            #pragma unroll
            for (int g = 0; g < 2; g++){
                const float* Ag = Ak + g*16*36;
                a[g][0] = __float_as_uint(Ag[0]);
                a[g][1] = __float_as_uint(Ag[8*36]);
                a[g][2] = __float_as_uint(Ag[4]);
                a[g][3] = __float_as_uint(Ag[8*36 + 4]);
            }
            const float* Bk = Bb + ks*8*264;
            #pragma unroll
            for (int f = 0; f < 4; f++){
                b[f][0] = __float_as_uint(Bk[f*8]);
                b[f][1] = __float_as_uint(Bk[4*264 + f*8]);
            }
            #pragma unroll
            for (int g = 0; g < 2; g++)
                #pragma unroll
                for (int f = 0; f < 4; f++)
                    mma_tf32(acc[g][f], a[g], b[f]);
        }
        if (c < 7) CPA_WAIT0();
        __syncthreads();
    }

    #pragma unroll
    for (int f = 0; f < 4; f++){
        float b0 = bias[n0 + wn*32 + f*8 + 2*q];
        float b1 = bias[n0 + wn*32 + f*8 + 2*q + 1];
        #pragma unroll
        for (int g = 0; g < 2; g++){
            acc[g][f][0] += b0; acc[g][f][1] += b1;
            acc[g][f][2] += b0; acc[g][f][3] += b1;
        }
    }

    if (do_ln){
        #pragma unroll
        for (int g = 0; g < 2; g++)
            #pragma unroll
            for (int h = 0; h < 2; h++){
                float s1 = 0.f, s2 = 0.f;
                #pragma unroll
                for (int f = 0; f < 4; f++){
                    float v0 = acc[g][f][2*h], v1 = acc[g][f][2*h + 1];
                    s1 += v0 + v1; s2 += v0*v0 + v1*v1;
                }
                s1 += __shfl_xor_sync(0xffffffffu, s1, 1);
                s2 += __shfl_xor_sync(0xffffffffu, s2, 1);
                s1 += __shfl_xor_sync(0xffffffffu, s1, 2);
                s2 += __shfl_xor_sync(0xffffffffu, s2, 2);
                if (q == 0){
                    int rl = wm*32 + g*16 + h*8 + r4;
                    s_red[rl][wn][0] = s1; s_red[rl][wn][1] = s2;
                }
            }
        __syncthreads();
        #pragma unroll
        for (int g = 0; g < 2; g++)
            #pragma unroll
            for (int h = 0; h < 2; h++){
                int rl = wm*32 + g*16 + h*8 + r4;
                float t1 = 0.f, t2 = 0.f;
                #pragma unroll
                for (int j = 0; j < 8; j++){ t1 += s_red[rl][j][0]; t2 += s_red[rl][j][1]; }
                float mean = t1 * (1.f/256.f);
                float var  = t2 * (1.f/256.f) - mean*mean;
                float rstd = rsqrtf(var + 1e-5f);
                #pragma unroll
                for (int f = 0; f < 4; f++){
                    acc[g][f][2*h]   = (acc[g][f][2*h]   - mean) * rstd;
                    acc[g][f][2*h+1] = (acc[g][f][2*h+1] - mean) * rstd;
                }
            }
    }

    #pragma unroll
    for (int g = 0; g < 2; g++)
        #pragma unroll
        for (int h = 0; h < 2; h++){
            int row = m0 + wm*32 + g*16 + h*8 + r4;
            float* op = outp + (size_t)row*N + n0 + wn*32 + 2*q;
            #pragma unroll
            for (int f = 0; f < 4; f++){
                float2 o2; o2.x = acc[g][f][2*h]; o2.y = acc[g][f][2*h+1];
                *(float2*)(op + f*8) = o2;
            }
        }
    __syncthreads();
}

// ---------- step phase (FFMA2): block=(b, 8 j), 512 threads ----------
__device__ void step_phase(const float* __restrict__ A, const float* __restrict__ Wout,
                           const float* __restrict__ bout, int iter, char* dyn)
{
    ull (*As)[8] = (ull(*)[8])dyn;
    Step2Sm* p2  = (Step2Sm*)dyn;

    const int t  = threadIdx.x;
    const int b  = blockIdx.x >> 3;
    const int j0 = (blockIdx.x & 7) * 8;
    const int row0 = b*64 + j0;

    const float* Ab = A + b*32768 + j0*8;
    #pragma unroll
    for (int idx = 0; idx < 4; idx++){
        int e = idx*512 + t;
        int kp = e >> 3, jj = e & 7;
        int k0 = kp*2;
        int base = (k0 >> 3)*512 + jj*8 + (k0 & 7);
        As[kp][jj] = packxy(Ab[base], Ab[base + 1]);
    }
    __syncthreads();

    const int tx = t & 127;
    const int ty = t >> 7;
    ull acc[8][2];
    #pragma unroll
    for (int jj = 0; jj < 8; jj++){ acc[jj][0] = 0ull; acc[jj][1] = 0ull; }

    const float* pb = g_p + (size_t)(b*64 + ty*16)*2048 + tx;
    #pragma unroll 2
    for (int ii = 0; ii < 16; ii++){
        const float* pr = pb + ii*2048;
        #pragma unroll
        for (int hp = 0; hp < 4; hp++){
            ull p0 = packxy(pr[hp*512],       pr[hp*512 + 256]);
            ull p1 = packxy(pr[hp*512 + 128], pr[hp*512 + 384]);
            const int kp = (ty*16 + ii)*4 + hp;
            ulonglong2 A01 = *(const ulonglong2*)&As[kp][0];
            ulonglong2 A23 = *(const ulonglong2*)&As[kp][2];
            ulonglong2 A45 = *(const ulonglong2*)&As[kp][4];
            ulonglong2 A67 = *(const ulonglong2*)&As[kp][6];
            ffma2(acc[0][0], A01.x, p0); ffma2(acc[0][1], A01.x, p1);
            ffma2(acc[1][0], A01.y, p0); ffma2(acc[1][1], A01.y, p1);
            ffma2(acc[2][0], A23.x, p0); ffma2(acc[2][1], A23.x, p1);
            ffma2(acc[3][0], A23.y, p0); ffma2(acc[3][1], A23.y, p1);
            ffma2(acc[4][0], A45.x, p0); ffma2(acc[4][1], A45.x, p1);
            ffma2(acc[5][0], A45.y, p0); ffma2(acc[5][1], A45.y, p1);
            ffma2(acc[6][0], A67.x, p0); ffma2(acc[6][1], A67.x, p1);
            ffma2(acc[7][0], A67.y, p0); ffma2(acc[7][1], A67.y, p1);
        }
    }
    __syncthreads();
    #pragma unroll
    for (int jj = 0; jj < 8; jj++){
        float2 u0 = unpack2(acc[jj][0]);
        float2 u1 = unpack2(acc[jj][1]);
        p2->ls[ty][jj][tx]       = u0.x + u0.y;
        p2->ls[ty][jj][tx + 128] = u1.x + u1.y;
    }
    __syncthreads();

    const int w = t >> 5, lane = t & 31;
    if (w < 8){
        const int r = w;
        const float* iorow = g_io + (size_t)(row0 + r)*768;
        float hv2[8];
        float s = 0.f;
        #pragma unroll
        for (int qq = 0; qq < 8; qq++){
            int d = qq*32 + lane;
            float x = p2->ls[0][r][d] + p2->ls[1][r][d]
                    + p2->ls[2][r][d] + p2->ls[3][r][d];
            x = x - tanhf(x);
            x += iorow[512 + d];
            hv2[qq] = x;
            s += x;
        }
        #pragma unroll
        for (int o = 16; o > 0; o >>= 1) s += __shfl_xor_sync(0xffffffffu, s, o);
        float mean = s * (1.f/256.f);
        float qv = 0.f;
        #pragma unroll
        for (int qq = 0; qq < 8; qq++){ float d = hv2[qq]-mean; qv += d*d; }
        #pragma unroll
        for (int o = 16; o > 0; o >>= 1) qv += __shfl_xor_sync(0xffffffffu, qv, o);
        float rr = rsqrtf(qv * (1.f/256.f) + 1e-5f);
        #pragma unroll
        for (int qq = 0; qq < 8; qq++){
            int d = qq*32 + lane;
            float lnv = (hv2[qq]-mean)*rr;
            float g = fmaf(iorow[d], lnv, iorow[256+d]);
            p2->hsm[d][r] = fmaxf(g, 0.f);
        }
    }
    __syncthreads();

    // phase 3: y = tanh(h @ Wout + b); k split across thread halves,
    // Wout read in its ORIGINAL [k][n] layout (fully coalesced LDG.32)
    const int n    = t & 255;
    const int half = t >> 8;              // k in [half*128, half*128+128)
    ull yacc[4] = {0ull, 0ull, 0ull, 0ull};
    const float* wcol = Wout + (size_t)half*128*256 + n;
    #pragma unroll 4
    for (int k = 0; k < 128; k++){
        ull w2 = pack2(wcol[(size_t)k*256]);
        ulonglong2 h01 = *(const ulonglong2*)&p2->hsm[half*128 + k][0];  // rows 0-3
        ulonglong2 h23 = *(const ulonglong2*)&p2->hsm[half*128 + k][4];  // rows 4-7
        ffma2(yacc[0], h01.x, w2);
        ffma2(yacc[1], h01.y, w2);
        ffma2(yacc[2], h23.x, w2);
        ffma2(yacc[3], h23.y, w2);
    }
    // cross-half combine via smem (reuse ls region — dead after phase 2)
    ull (*red)[4] = (ull(*)[4])dyn;       // [256][4] ull = 8KB, below hsm (32KB+)
    if (half == 0){
        red[n][0] = yacc[0]; red[n][1] = yacc[1];
        red[n][2] = yacc[2]; red[n][3] = yacc[3];
    }
    __syncthreads();
    if (half == 1){
        float bo = bout[n];
        bool masked = (iter > g_len[b]);
        #pragma unroll
        for (int q2 = 0; q2 < 4; q2++){
            float2 u = unpack2(yacc[q2]);
            float2 v = unpack2(red[n][q2]);
            float y0 = masked ? 0.f : to_tf32(tanhf(u.x + v.x + bo));
            float y1 = masked ? 0.f : to_tf32(tanhf(u.y + v.y + bo));
            g_h[(size_t)(row0 + 2*q2    )*256 + n] = y0;
            g_h[(size_t)(row0 + 2*q2 + 1)*256 + n] = y1;
        }
    }
}

// ---------- single persistent kernel ----------
__global__ void __launch_bounds__(512) fused_kernel(
    const int* __restrict__ tokens, const float* __restrict__ A,
    const float* __restrict__ root, const float* __restrict__ emb,
    const float* __restrict__ Wp,   const float* __restrict__ bp,
    const float* __restrict__ Win,  const float* __restrict__ bin,
    const float* __restrict__ Wout, const float* __restrict__ bout,
    float* __restrict__ out)
{
    extern __shared__ char smraw[];
    char* dyn = (char*)((((size_t)smraw) + 1023) & ~(size_t)1023);
    __shared__ float s_red[64][8][2];

    const int bid = blockIdx.x;
    const int t = threadIdx.x;
    const int b = bid >> 3, r = bid & 7;

    // prologue
    {
        int idx = r*512 + t;                 // batch b: 4096 float4
        int l = idx >> 6;
        int c4 = (idx & 63) * 4;
        int row = b*64 + l;
        int tok = tokens[l*16 + b];
        float4 e4 = *(const float4*)&emb[(size_t)tok*256 + c4];
        e4.x = to_tf32(e4.x); e4.y = to_tf32(e4.y); e4.z = to_tf32(e4.z); e4.w = to_tf32(e4.w);
        *(float4*)&g_x[(size_t)row*256 + c4] = e4;
        float4 z; z.x=z.y=z.z=z.w=0.f;
        *(float4*)&g_h[(size_t)row*256 + c4] = z;
        if (r == 0 && t == 0){
            int c = 0;
            for (int l2 = 0; l2 < 64; l2++) c += (tokens[l2*16 + b] != 0);
            g_len[b] = c;
        }
        int gidx = bid*512 + t;              // 0..65535
        #pragma unroll
        for (int i = 0; i < 2; i++){         // WpR: 131072 float4
            int e = gidx + i*65536;
            float4 v = *(const float4*)&Wp[(size_t)e*4];
            v.x = to_tf32(v.x); v.y = to_tf32(v.y); v.z = to_tf32(v.z); v.w = to_tf32(v.w);
            *(float4*)&g_wpR[(size_t)e*4] = v;
        }
        if (gidx < 49152){                   // WinR
            float4 v = *(const float4*)&Win[(size_t)gidx*4];
            v.x = to_tf32(v.x); v.y = to_tf32(v.y); v.z = to_tf32(v.z); v.w = to_tf32(v.w);
            *(float4*)&g_winR[(size_t)gidx*4] = v;
        }
    }
    grid_sync();   // ONE global sync: weights visible to all groups

    // hoisted in_proj (group-local: blocks r<3 cover N=768)
    if (r < 3)
        gemm_mma(g_x, g_winR, bin, g_io, 768, b*64, r*256, false, dyn, s_red);
    group_sync(b);

    // 64-step recurrence — fully batch-local
    for (int it = 0; it < 64; it++){
        gemm_mma(g_h, g_wpR, bp, g_p, 2048, b*64, r*256, true, dyn, s_red);
        group_sync(b);
        step_phase(A, Wout, bout, 64 - it, dyn);
        group_sync(b);
    }

    // epilogue: out[b][d] = sum_i h[b,i,d] * root[b,i]
    if (r == 0 && t < 256){
        float s = 0.f;
        #pragma unroll 8
        for (int i = 0; i < 64; i++)
            s += g_h[(size_t)(b*64 + i)*256 + t] * root[b*64 + i];
        out[b*256 + t] = s;
    }
}

extern "C" void kernel_launch(void* const* d_in, const int* in_sizes, int n_in,
                              void* d_out, int out_size)
{
    const int*   tokens = (const int*)  d_in[0];
    const float* A      = (const float*)d_in[1];
    const float* root   = (const float*)d_in[2];
    const float* emb    = (const float*)d_in[3];
    const float* Wp     = (const float*)d_in[4];
    const float* bp     = (const float*)d_in[5];
    const float* Win    = (const float*)d_in[6];
    const float* bin    = (const float*)d_in[7];
    const float* Wout   = (const float*)d_in[8];
    const float* bout   = (const float*)d_in[9];

    cudaFuncSetAttribute(fused_kernel, cudaFuncAttributeMaxDynamicSharedMemorySize, SMEM_DYN);
    fused_kernel<<<NBLOCKS, 512, SMEM_DYN>>>(tokens, A, root, emb, Wp, bp, Win, bin,
                                             Wout, bout, (float*)d_out);
}

// round 10
// speedup vs baseline: 1.4030x; 1.0285x over previous
#include <cuda_runtime.h>

#define NBLOCKS 128
typedef unsigned long long ull;

__device__ __align__(16) float g_x   [1024*256];
__device__ __align__(16) float g_io  [1024*768];        // shift|scale|proj_x
__device__ __align__(16) float g_part[16*8*64*256];     // [b][rel][j][d] partial lin_sum
__device__ __align__(16) float g_h   [1024*256];
__device__ __align__(16) float g_wpR [256*2048];        // Wp  tf32-rounded [k][n]
__device__ __align__(16) float g_winR[256*768];         // Win tf32-rounded [k][n]
__device__ int g_len[16];
__device__ unsigned g_cnt = 0, g_gen = 0;
__device__ unsigned g_gcnt[16*32];
__device__ unsigned g_ggen[16*32];

// ---------- helpers ----------
__device__ __forceinline__ ull pack2(float v){
    ull r; asm("mov.b64 %0, {%1, %1};" : "=l"(r) : "f"(v)); return r;
}
__device__ __forceinline__ float2 unpack2(ull v){
    float2 r; asm("mov.b64 {%0, %1}, %2;" : "=f"(r.x), "=f"(r.y) : "l"(v)); return r;
}
__device__ __forceinline__ void ffma2(ull& d, ull a, ull b){
    asm("fma.rn.f32x2 %0, %1, %2, %0;" : "+l"(d) : "l"(a), "l"(b));
}
__device__ __forceinline__ void cpa16(void* s, const void* g){
    unsigned ss = (unsigned)__cvta_generic_to_shared(s);
    asm volatile("cp.async.cg.shared.global [%0], [%1], 16;\n" :: "r"(ss), "l"(g));
}
#define CPA_COMMIT() asm volatile("cp.async.commit_group;\n" ::: "memory")
#define CPA_WAIT0()  asm volatile("cp.async.wait_group 0;\n" ::: "memory")

__device__ __forceinline__ float to_tf32(float x){
    float r; asm("cvt.rna.tf32.f32 %0, %1;" : "=f"(r) : "f"(x)); return r;
}

// legacy HMMA m16n8k8 tf32 (base sm_103-legal)
__device__ __forceinline__ void mma_tf32(float* d, const unsigned* a, const unsigned* b){
    asm volatile(
        "mma.sync.aligned.m16n8k8.row.col.f32.tf32.tf32.f32 "
        "{%0,%1,%2,%3}, {%4,%5,%6,%7}, {%8,%9}, {%0,%1,%2,%3};"
        : "+f"(d[0]), "+f"(d[1]), "+f"(d[2]), "+f"(d[3])
        : "r"(a[0]), "r"(a[1]), "r"(a[2]), "r"(a[3]), "r"(b[0]), "r"(b[1]));
}

// ---------- dynamic smem layout ----------
// [0      .. 18432)  gemm Asm [2][64*36] | einsum As_hi [64][68] | step StepSm
// [18432  .. 86016)  gemm Bsm [2][32*264] | p_lo [64][264]
// [86016  ..153600)  p_hi [64][264]
// [153600 ..171008)  einsum As_lo [64][68]
#define OFF_BSM   18432
#define OFF_PHI   86016
#define OFF_ALO   153600
#define SMEM_DYN  172032
struct StepSm { float hsm[256][12]; ull red[256][4]; };   // 20.5 KB (step phase only)

// ---------- barriers ----------
__device__ __forceinline__ void grid_sync(){
    __threadfence();
    __syncthreads();
    if (threadIdx.x == 0){
        unsigned my = *(volatile unsigned*)&g_gen;
        if (atomicAdd(&g_cnt, 1u) == NBLOCKS - 1u){
            g_cnt = 0;
            __threadfence();
            atomicAdd(&g_gen, 1u);
        } else {
            while (*(volatile unsigned*)&g_gen == my) __nanosleep(64);
        }
        __threadfence();
    }
    __syncthreads();
}

__device__ __forceinline__ void group_sync(int b){
    __threadfence();
    __syncthreads();
    if (threadIdx.x == 0){
        volatile unsigned* gen = &g_ggen[b*32];
        unsigned my = *gen;
        if (atomicAdd(&g_gcnt[b*32], 1u) == 7u){
            g_gcnt[b*32] = 0;
            __threadfence();
            atomicAdd((unsigned*)&g_ggen[b*32], 1u);
        } else {
            while (*gen == my) __nanosleep(32);
        }
        __threadfence();
    }
    __syncthreads();
}

// ---------- HMMA GEMM tile: 64(m) x 256(n), K=256 ----------
// mode 0: +bias, STG to outp. mode 1: +bias, LN, STS hi/lo tf32 split to smem p.
__device__ void gemm_mma(const float* __restrict__ Asrc, const float* __restrict__ Bsrc,
                         const float* __restrict__ bias, float* __restrict__ outp,
                         int N, int m0, int n0, int mode, char* dyn,
                         float (*s_red)[8][2])
{
    const int t = threadIdx.x, w = t >> 5, lane = t & 31;
    const int wm = w & 1, wn = w >> 1;
    const int r4 = lane >> 2, q = lane & 3;

    float* Asm = (float*)dyn;                // [2][64*36]
    float* Bsm = (float*)(dyn + OFF_BSM);    // [2][32*264]

    float acc[2][4][4];
    #pragma unroll
    for (int g = 0; g < 2; g++)
        #pragma unroll
        for (int f = 0; f < 4; f++)
            #pragma unroll
            for (int rr = 0; rr < 4; rr++) acc[g][f][rr] = 0.f;

    const int am = t >> 3, ak4 = (t & 7) * 4;

    cpa16(Asm + am*36 + ak4, Asrc + (size_t)(m0 + am)*256 + ak4);
    #pragma unroll
    for (int i = 0; i < 4; i++){
        int e = t + i*512, k = e >> 6, n4 = (e & 63) * 4;
        cpa16(Bsm + k*264 + n4, Bsrc + (size_t)k*N + n0 + n4);
    }
    CPA_COMMIT(); CPA_WAIT0();
    __syncthreads();

    for (int c = 0; c < 8; c++){
        const int buf = c & 1;
        if (c < 7){
            const int nb = buf ^ 1;
            cpa16(Asm + nb*2304 + am*36 + ak4,
                  Asrc + (size_t)(m0 + am)*256 + (c+1)*32 + ak4);
            #pragma unroll
            for (int i = 0; i < 4; i++){
                int e = t + i*512, k = e >> 6, n4 = (e & 63) * 4;
                cpa16(Bsm + nb*8448 + k*264 + n4,
                      Bsrc + (size_t)((c+1)*32 + k)*N + n0 + n4);
            }
            CPA_COMMIT();
        }
        const float* Ab = Asm + buf*2304 + (wm*32 + r4)*36 + q;
        const float* Bb = Bsm + buf*8448 + q*264 + wn*32 + r4;
        #pragma unroll
        for (int ks = 0; ks < 4; ks++){
            unsigned a[2][4], b[4][2];
            const float* Ak = Ab + ks*8;
            #pragma unroll
            for (int g = 0; g < 2; g++){
                const float* Ag = Ak + g*16*36;
                a[g][0] = __float_as_uint(Ag[0]);
                a[g][1] = __float_as_uint(Ag[8*36]);
                a[g][2] = __float_as_uint(Ag[4]);
                a[g][3] = __float_as_uint(Ag[8*36 + 4]);
            }
            const float* Bk = Bb + ks*8*264;
            #pragma unroll
            for (int f = 0; f < 4; f++){
                b[f][0] = __float_as_uint(Bk[f*8]);
                b[f][1] = __float_as_uint(Bk[4*264 + f*8]);
            }
            #pragma unroll
            for (int g = 0; g < 2; g++)
                #pragma unroll
                for (int f = 0; f < 4; f++)
                    mma_tf32(acc[g][f], a[g], b[f]);
        }
        if (c < 7) CPA_WAIT0();
        __syncthreads();
    }

    #pragma unroll
    for (int f = 0; f < 4; f++){
        float b0 = bias[n0 + wn*32 + f*8 + 2*q];
        float b1 = bias[n0 + wn*32 + f*8 + 2*q + 1];
        #pragma unroll
        for (int g = 0; g < 2; g++){
            acc[g][f][0] += b0; acc[g][f][1] += b1;
            acc[g][f][2] += b0; acc[g][f][3] += b1;
        }
    }

    if (mode == 1){
        // per-row LN over 256 cols
        #pragma unroll
        for (int g = 0; g < 2; g++)
            #pragma unroll
            for (int h = 0; h < 2; h++){
                float s1 = 0.f, s2 = 0.f;
                #pragma unroll
                for (int f = 0; f < 4; f++){
                    float v0 = acc[g][f][2*h], v1 = acc[g][f][2*h + 1];
                    s1 += v0 + v1; s2 += v0*v0 + v1*v1;
                }
                s1 += __shfl_xor_sync(0xffffffffu, s1, 1);
                s2 += __shfl_xor_sync(0xffffffffu, s2, 1);
                s1 += __shfl_xor_sync(0xffffffffu, s1, 2);
                s2 += __shfl_xor_sync(0xffffffffu, s2, 2);
                if (q == 0){
                    int rl = wm*32 + g*16 + h*8 + r4;
                    s_red[rl][wn][0] = s1; s_red[rl][wn][1] = s2;
                }
            }
        __syncthreads();
        float* ph = (float*)(dyn + OFF_PHI);
        float* pl = (float*)(dyn + OFF_BSM);     // Bsm dead now
        #pragma unroll
        for (int g = 0; g < 2; g++)
            #pragma unroll
            for (int h = 0; h < 2; h++){
                int rl = wm*32 + g*16 + h*8 + r4;
                float t1 = 0.f, t2 = 0.f;
                #pragma unroll
                for (int j = 0; j < 8; j++){ t1 += s_red[rl][j][0]; t2 += s_red[rl][j][1]; }
                float mean = t1 * (1.f/256.f);
                float var  = t2 * (1.f/256.f) - mean*mean;
                float rstd = rsqrtf(var + 1e-5f);
                int base = rl*264 + wn*32 + 2*q;
                #pragma unroll
                for (int f = 0; f < 4; f++){
                    float v0 = (acc[g][f][2*h]   - mean) * rstd;
                    float v1 = (acc[g][f][2*h+1] - mean) * rstd;
                    float h0 = to_tf32(v0), h1 = to_tf32(v1);
                    float2 hv; hv.x = h0; hv.y = h1;
                    float2 lv; lv.x = to_tf32(v0 - h0); lv.y = to_tf32(v1 - h1);
                    *(float2*)(ph + base + f*8) = hv;
                    *(float2*)(pl + base + f*8) = lv;
                }
            }
    } else {
        #pragma unroll
        for (int g = 0; g < 2; g++)
            #pragma unroll
            for (int h = 0; h < 2; h++){
                int row = m0 + wm*32 + g*16 + h*8 + r4;
                float* op = outp + (size_t)row*N + n0 + wn*32 + 2*q;
                #pragma unroll
                for (int f = 0; f < 4; f++){
                    float2 o2; o2.x = acc[g][f][2*h]; o2.y = acc[g][f][2*h+1];
                    *(float2*)(op + f*8) = o2;
                }
            }
    }
    __syncthreads();
}

// ---------- einsum (3xTF32 HMMA): partial[j][d] = sum_i A[b,i,j,r] * p_r[i][d] ----------
// M=64(j), K=64(i), N=256(d). p_r hi/lo already in smem from gemm epilogue.
__device__ void einsum_mma(const float* __restrict__ A, int b, int r, char* dyn)
{
    const int t = threadIdx.x, w = t >> 5, lane = t & 31;
    const int wm = w & 1, wn = w >> 1;
    const int r4 = lane >> 2, q = lane & 3;

    float* As_h = (float*)dyn;               // [64][68] (Asm region, dead)
    float* As_l = (float*)(dyn + OFF_ALO);   // [64][68]
    float* P_h  = (float*)(dyn + OFF_PHI);
    float* P_l  = (float*)(dyn + OFF_BSM);

    // stage A_e transposed + hi/lo split: As[j][i] = A[b,i,j,r]
    const float* Ab = A + (size_t)b*32768 + r;
    #pragma unroll
    for (int pass = 0; pass < 8; pass++){
        int e = pass*512 + t;
        int j = e & 63, i = e >> 6;
        float a = Ab[(size_t)i*512 + j*8];
        float hi = to_tf32(a);
        As_h[j*68 + i] = hi;
        As_l[j*68 + i] = to_tf32(a - hi);
    }
    __syncthreads();   // also orders gemm's p STS before reads

    float acc[2][4][4];
    #pragma unroll
    for (int g = 0; g < 2; g++)
        #pragma unroll
        for (int f = 0; f < 4; f++)
            #pragma unroll
            for (int rr = 0; rr < 4; rr++) acc[g][f][rr] = 0.f;

    // 3 passes: Ah*Ph, Ah*Pl, Al*Ph
    #pragma unroll
    for (int pass = 0; pass < 3; pass++){
        const float* Ax = (pass == 2) ? As_l : As_h;
        const float* Px = (pass == 1) ? P_l  : P_h;
        const float* Abase = Ax + (wm*32 + r4)*68 + q;
        const float* Bbase = Px + q*264 + wn*32 + r4;
        #pragma unroll
        for (int ks = 0; ks < 8; ks++){
            unsigned a[2][4], bfr[4][2];
            const float* Ak = Abase + ks*8;
            #pragma unroll
            for (int g = 0; g < 2; g++){
                const float* Ag = Ak + g*16*68;
                a[g][0] = __float_as_uint(Ag[0]);
                a[g][1] = __float_as_uint(Ag[8*68]);
                a[g][2] = __float_as_uint(Ag[4]);
                a[g][3] = __float_as_uint(Ag[8*68 + 4]);
            }
            const float* Bk = Bbase + ks*8*264;
            #pragma unroll
            for (int f = 0; f < 4; f++){
                bfr[f][0] = __float_as_uint(Bk[f*8]);
                bfr[f][1] = __float_as_uint(Bk[4*264 + f*8]);
            }
            #pragma unroll
            for (int g = 0; g < 2; g++)
                #pragma unroll
                for (int f = 0; f < 4; f++)
                    mma_tf32(acc[g][f], a[g], bfr[f]);
        }
    }

    // write partial to global
    float* pb = g_part + (size_t)(b*8 + r)*64*256;
    #pragma unroll
    for (int g = 0; g < 2; g++)
        #pragma unroll
        for (int h = 0; h < 2; h++){
            int j = wm*32 + g*16 + h*8 + r4;
            float* op = pb + (size_t)j*256 + wn*32 + 2*q;
            #pragma unroll
            for (int f = 0; f < 4; f++){
                float2 o2; o2.x = acc[g][f][2*h]; o2.y = acc[g][f][2*h+1];
                *(float2*)(op + f*8) = o2;
            }
        }
    __syncthreads();
}

// ---------- step phases 2+3: shrink+LN+gate, then h@Wout ----------
__device__ void step23(const float* __restrict__ Wout, const float* __restrict__ bout,
                       int iter, char* dyn)
{
    StepSm* sm = (StepSm*)dyn;
    const int t  = threadIdx.x;
    const int b  = blockIdx.x >> 3;
    const int j0 = (blockIdx.x & 7) * 8;
    const int row0 = b*64 + j0;
    const int w = t >> 5, lane = t & 31;

    if (w < 8){
        const int r = w;
        const int j = j0 + r;
        const float* iorow = g_io + (size_t)(row0 + r)*768;
        const float* pp = g_part + (size_t)(b*8)*64*256 + (size_t)j*256;
        float hv2[8];
        float s = 0.f;
        #pragma unroll
        for (int qq = 0; qq < 8; qq++){
            int d = qq*32 + lane;
            float x = 0.f;
            #pragma unroll
            for (int rel = 0; rel < 8; rel++)
                x += pp[(size_t)rel*64*256 + d];
            x = x - tanhf(x);
            x += iorow[512 + d];
            hv2[qq] = x;
            s += x;
        }
        #pragma unroll
        for (int o = 16; o > 0; o >>= 1) s += __shfl_xor_sync(0xffffffffu, s, o);
        float mean = s * (1.f/256.f);
        float qv = 0.f;
        #pragma unroll
        for (int qq = 0; qq < 8; qq++){ float d = hv2[qq]-mean; qv += d*d; }
        #pragma unroll
        for (int o = 16; o > 0; o >>= 1) qv += __shfl_xor_sync(0xffffffffu, qv, o);
        float rr = rsqrtf(qv * (1.f/256.f) + 1e-5f);
        #pragma unroll
        for (int qq = 0; qq < 8; qq++){
            int d = qq*32 + lane;
            float lnv = (hv2[qq]-mean)*rr;
            float g = fmaf(iorow[d], lnv, iorow[256+d]);
            sm->hsm[d][r] = fmaxf(g, 0.f);
        }
    }
    __syncthreads();

    // phase 3: y = tanh(h @ Wout + b); k split across thread halves, coalesced Wout
    const int n    = t & 255;
    const int half = t >> 8;
    ull yacc[4] = {0ull, 0ull, 0ull, 0ull};
    const float* wcol = Wout + (size_t)half*128*256 + n;
    #pragma unroll 4
    for (int k = 0; k < 128; k++){
        ull w2 = pack2(wcol[(size_t)k*256]);
        ulonglong2 h01 = *(const ulonglong2*)&sm->hsm[half*128 + k][0];
        ulonglong2 h23 = *(const ulonglong2*)&sm->hsm[half*128 + k][4];
        ffma2(yacc[0], h01.x, w2);
        ffma2(yacc[1], h01.y, w2);
        ffma2(yacc[2], h23.x, w2);
        ffma2(yacc[3], h23.y, w2);
    }
    if (half == 0){
        sm->red[n][0] = yacc[0]; sm->red[n][1] = yacc[1];
        sm->red[n][2] = yacc[2]; sm->red[n][3] = yacc[3];
    }
    __syncthreads();
    if (half == 1){
        float bo = bout[n];
        bool masked = (iter > g_len[b]);
        #pragma unroll
        for (int q2 = 0; q2 < 4; q2++){
            float2 u = unpack2(yacc[q2]);
            float2 v = unpack2(sm->red[n][q2]);
            float y0 = masked ? 0.f : to_tf32(tanhf(u.x + v.x + bo));
            float y1 = masked ? 0.f : to_tf32(tanhf(u.y + v.y + bo));
            g_h[(size_t)(row0 + 2*q2    )*256 + n] = y0;
            g_h[(size_t)(row0 + 2*q2 + 1)*256 + n] = y1;
        }
    }
    __syncthreads();
}

// ---------- single persistent kernel ----------
__global__ void __launch_bounds__(512) fused_kernel(
    const int* __restrict__ tokens, const float* __restrict__ A,
    const float* __restrict__ root, const float* __restrict__ emb,
    const float* __restrict__ Wp,   const float* __restrict__ bp,
    const float* __restrict__ Win,  const float* __restrict__ bin,
    const float* __restrict__ Wout, const float* __restrict__ bout,
    float* __restrict__ out)
{
    extern __shared__ char smraw[];
    char* dyn = (char*)((((size_t)smraw) + 1023) & ~(size_t)1023);
    __shared__ float s_red[64][8][2];

    const int bid = blockIdx.x;
    const int t = threadIdx.x;
    const int b = bid >> 3, r = bid & 7;

    // prologue
    {
        int idx = r*512 + t;
        int l = idx >> 6;
        int c4 = (idx & 63) * 4;
        int row = b*64 + l;
        int tok = tokens[l*16 + b];
        float4 e4 = *(const float4*)&emb[(size_t)tok*256 + c4];
        e4.x = to_tf32(e4.x); e4.y = to_tf32(e4.y); e4.z = to_tf32(e4.z); e4.w = to_tf32(e4.w);
        *(float4*)&g_x[(size_t)row*256 + c4] = e4;
        float4 z; z.x=z.y=z.z=z.w=0.f;
        *(float4*)&g_h[(size_t)row*256 + c4] = z;
        if (r == 0 && t == 0){
            int c = 0;
            for (int l2 = 0; l2 < 64; l2++) c += (tokens[l2*16 + b] != 0);
            g_len[b] = c;
        }
        int gidx = bid*512 + t;
        #pragma unroll
        for (int i = 0; i < 2; i++){
            int e = gidx + i*65536;
            float4 v = *(const float4*)&Wp[(size_t)e*4];
            v.x = to_tf32(v.x); v.y = to_tf32(v.y); v.z = to_tf32(v.z); v.w = to_tf32(v.w);
            *(float4*)&g_wpR[(size_t)e*4] = v;
        }
        if (gidx < 49152){
            float4 v = *(const float4*)&Win[(size_t)gidx*4];
            v.x = to_tf32(v.x); v.y = to_tf32(v.y); v.z = to_tf32(v.z); v.w = to_tf32(v.w);
            *(float4*)&g_winR[(size_t)gidx*4] = v;
        }
    }
    grid_sync();

    // hoisted in_proj (blocks r<3 cover N=768)
    if (r < 3)
        gemm_mma(g_x, g_winR, bin, g_io, 768, b*64, r*256, 0, dyn, s_red);
    group_sync(b);

    // 64-step recurrence — batch-local
    for (int it = 0; it < 64; it++){
        gemm_mma(g_h, g_wpR, bp, (float*)0, 2048, b*64, r*256, 1, dyn, s_red);
        einsum_mma(A, b, r, dyn);
        group_sync(b);
        step23(Wout, bout, 64 - it, dyn);
        group_sync(b);
    }

    // epilogue
    if (r == 0 && t < 256){
        float s = 0.f;
        #pragma unroll 8
        for (int i = 0; i < 64; i++)
            s += g_h[(size_t)(b*64 + i)*256 + t] * root[b*64 + i];
        out[b*256 + t] = s;
    }
}

extern "C" void kernel_launch(void* const* d_in, const int* in_sizes, int n_in,
                              void* d_out, int out_size)
{
    const int*   tokens = (const int*)  d_in[0];
    const float* A      = (const float*)d_in[1];
    const float* root   = (const float*)d_in[2];
    const float* emb    = (const float*)d_in[3];
    const float* Wp     = (const float*)d_in[4];
    const float* bp     = (const float*)d_in[5];
    const float* Win    = (const float*)d_in[6];
    const float* bin    = (const float*)d_in[7];
    const float* Wout   = (const float*)d_in[8];
    const float* bout   = (const float*)d_in[9];

    cudaFuncSetAttribute(fused_kernel, cudaFuncAttributeMaxDynamicSharedMemorySize, SMEM_DYN);
    fused_kernel<<<NBLOCKS, 512, SMEM_DYN>>>(tokens, A, root, emb, Wp, bp, Win, bin,
                                             Wout, bout, (float*)d_out);
}

// round 11
// speedup vs baseline: 1.7191x; 1.2253x over previous
#include <cuda_runtime.h>

#define NBLOCKS 128
typedef unsigned long long ull;

__device__ __align__(16) float g_x   [1024*256];
__device__ __align__(16) float g_io  [1024*768];        // shift|scale|proj_x
__device__ __align__(16) float g_part[16*8*64*256];     // [b][rel][j][d] partial lin_sum
__device__ __align__(16) float g_h   [1024*256];
__device__ __align__(16) float g_wpR [256*2048];        // Wp  tf32-rounded [k][n]
__device__ __align__(16) float g_winR[256*768];         // Win tf32-rounded [k][n]
__device__ int g_len[16];
__device__ unsigned g_cnt = 0, g_gen = 0;
__device__ unsigned g_gcnt[16*32];
__device__ unsigned g_ggen[16*32];

// ---------- helpers ----------
__device__ __forceinline__ ull pack2(float v){
    ull r; asm("mov.b64 %0, {%1, %1};" : "=l"(r) : "f"(v)); return r;
}
__device__ __forceinline__ float2 unpack2(ull v){
    float2 r; asm("mov.b64 {%0, %1}, %2;" : "=f"(r.x), "=f"(r.y) : "l"(v)); return r;
}
__device__ __forceinline__ void ffma2(ull& d, ull a, ull b){
    asm("fma.rn.f32x2 %0, %1, %2, %0;" : "+l"(d) : "l"(a), "l"(b));
}
__device__ __forceinline__ void cpa16(void* s, const void* g){
    unsigned ss = (unsigned)__cvta_generic_to_shared(s);
    asm volatile("cp.async.cg.shared.global [%0], [%1], 16;\n" :: "r"(ss), "l"(g));
}
#define CPA_COMMIT() asm volatile("cp.async.commit_group;\n" ::: "memory")
#define CPA_WAIT0()  asm volatile("cp.async.wait_group 0;\n" ::: "memory")

__device__ __forceinline__ float to_tf32(float x){
    float r; asm("cvt.rna.tf32.f32 %0, %1;" : "=f"(r) : "f"(x)); return r;
}

// legacy HMMA m16n8k8 tf32 (base sm_103-legal)
__device__ __forceinline__ void mma_tf32(float* d, const unsigned* a, const unsigned* b){
    asm volatile(
        "mma.sync.aligned.m16n8k8.row.col.f32.tf32.tf32.f32 "
        "{%0,%1,%2,%3}, {%4,%5,%6,%7}, {%8,%9}, {%0,%1,%2,%3};"
        : "+f"(d[0]), "+f"(d[1]), "+f"(d[2]), "+f"(d[3])
        : "r"(a[0]), "r"(a[1]), "r"(a[2]), "r"(a[3]), "r"(b[0]), "r"(b[1]));
}

// ---------- dynamic smem layout ----------
// [0      .. 18432)  gemm Asm [2][64*36] | step StepSm (20.6KB)
// [18432  .. 86016)  gemm Bsm [2][32*264] | p (single tf32) [64][264]
// [86016  ..103424)  einsum As [64][68]
#define OFF_BSM   18432
#define OFF_ASE   86016
#define SMEM_DYN  103424
struct StepSm { float hsm[256][12]; ull red[256][4]; float lnp[8][2][2]; };

// ---------- barriers ----------
__device__ __forceinline__ void grid_sync(){
    __threadfence();
    __syncthreads();
    if (threadIdx.x == 0){
        unsigned my = *(volatile unsigned*)&g_gen;
        if (atomicAdd(&g_cnt, 1u) == NBLOCKS - 1u){
            g_cnt = 0;
            __threadfence();
            atomicAdd(&g_gen, 1u);
        } else {
            while (*(volatile unsigned*)&g_gen == my) __nanosleep(64);
        }
        __threadfence();
    }
    __syncthreads();
}

__device__ __forceinline__ void group_sync(int b){
    __threadfence();
    __syncthreads();
    if (threadIdx.x == 0){
        volatile unsigned* gen = &g_ggen[b*32];
        unsigned my = *gen;
        if (atomicAdd(&g_gcnt[b*32], 1u) == 7u){
            g_gcnt[b*32] = 0;
            __threadfence();
            atomicAdd((unsigned*)&g_ggen[b*32], 1u);
        } else {
            while (*gen == my) __nanosleep(32);
        }
        __threadfence();
    }
    __syncthreads();
}

// ---------- HMMA GEMM tile: 64(m) x 256(n), K=256 ----------
// mode 0: +bias, STG to outp. mode 1: +bias, LN, STS tf32 p to smem.
__device__ void gemm_mma(const float* __restrict__ Asrc, const float* __restrict__ Bsrc,
                         const float* __restrict__ bias, float* __restrict__ outp,
                         int N, int m0, int n0, int mode, char* dyn,
                         float (*s_red)[8][2])
{
    const int t = threadIdx.x, w = t >> 5, lane = t & 31;
    const int wm = w & 1, wn = w >> 1;
    const int r4 = lane >> 2, q = lane & 3;

    float* Asm = (float*)dyn;                // [2][64*36]
    float* Bsm = (float*)(dyn + OFF_BSM);    // [2][32*264]

    float acc[2][4][4];
    #pragma unroll
    for (int g = 0; g < 2; g++)
        #pragma unroll
        for (int f = 0; f < 4; f++)
            #pragma unroll
            for (int rr = 0; rr < 4; rr++) acc[g][f][rr] = 0.f;

    const int am = t >> 3, ak4 = (t & 7) * 4;

    cpa16(Asm + am*36 + ak4, Asrc + (size_t)(m0 + am)*256 + ak4);
    #pragma unroll
    for (int i = 0; i < 4; i++){
        int e = t + i*512, k = e >> 6, n4 = (e & 63) * 4;
        cpa16(Bsm + k*264 + n4, Bsrc + (size_t)k*N + n0 + n4);
    }
    CPA_COMMIT(); CPA_WAIT0();
    __syncthreads();

    for (int c = 0; c < 8; c++){
        const int buf = c & 1;
        if (c < 7){
            const int nb = buf ^ 1;
            cpa16(Asm + nb*2304 + am*36 + ak4,
                  Asrc + (size_t)(m0 + am)*256 + (c+1)*32 + ak4);
            #pragma unroll
            for (int i = 0; i < 4; i++){
                int e = t + i*512, k = e >> 6, n4 = (e & 63) * 4;
                cpa16(Bsm + nb*8448 + k*264 + n4,
                      Bsrc + (size_t)((c+1)*32 + k)*N + n0 + n4);
            }
            CPA_COMMIT();
        }
        const float* Ab = Asm + buf*2304 + (wm*32 + r4)*36 + q;
        const float* Bb = Bsm + buf*8448 + q*264 + wn*32 + r4;
        #pragma unroll
        for (int ks = 0; ks < 4; ks++){
            unsigned a[2][4], b[4][2];
            const float* Ak = Ab + ks*8;
            #pragma unroll
            for (int g = 0; g < 2; g++){
                const float* Ag = Ak + g*16*36;
                a[g][0] = __float_as_uint(Ag[0]);
                a[g][1] = __float_as_uint(Ag[8*36]);
                a[g][2] = __float_as_uint(Ag[4]);
                a[g][3] = __float_as_uint(Ag[8*36 + 4]);
            }
            const float* Bk = Bb + ks*8*264;
            #pragma unroll
            for (int f = 0; f < 4; f++){
                b[f][0] = __float_as_uint(Bk[f*8]);
                b[f][1] = __float_as_uint(Bk[4*264 + f*8]);
            }
            #pragma unroll
            for (int g = 0; g < 2; g++)
                #pragma unroll
                for (int f = 0; f < 4; f++)
                    mma_tf32(acc[g][f], a[g], b[f]);
        }
        if (c < 7) CPA_WAIT0();
        __syncthreads();
    }

    #pragma unroll
    for (int f = 0; f < 4; f++){
        float b0 = bias[n0 + wn*32 + f*8 + 2*q];
        float b1 = bias[n0 + wn*32 + f*8 + 2*q + 1];
        #pragma unroll
        for (int g = 0; g < 2; g++){
            acc[g][f][0] += b0; acc[g][f][1] += b1;
            acc[g][f][2] += b0; acc[g][f][3] += b1;
        }
    }

    if (mode == 1){
        // per-row LN over 256 cols, then STS tf32 p into Bsm region (dead)
        #pragma unroll
        for (int g = 0; g < 2; g++)
            #pragma unroll
            for (int h = 0; h < 2; h++){
                float s1 = 0.f, s2 = 0.f;
                #pragma unroll
                for (int f = 0; f < 4; f++){
                    float v0 = acc[g][f][2*h], v1 = acc[g][f][2*h + 1];
                    s1 += v0 + v1; s2 += v0*v0 + v1*v1;
                }
                s1 += __shfl_xor_sync(0xffffffffu, s1, 1);
                s2 += __shfl_xor_sync(0xffffffffu, s2, 1);
                s1 += __shfl_xor_sync(0xffffffffu, s1, 2);
                s2 += __shfl_xor_sync(0xffffffffu, s2, 2);
                if (q == 0){
                    int rl = wm*32 + g*16 + h*8 + r4;
                    s_red[rl][wn][0] = s1; s_red[rl][wn][1] = s2;
                }
            }
        __syncthreads();
        float* P = (float*)(dyn + OFF_BSM);
        #pragma unroll
        for (int g = 0; g < 2; g++)
            #pragma unroll
            for (int h = 0; h < 2; h++){
                int rl = wm*32 + g*16 + h*8 + r4;
                float t1 = 0.f, t2 = 0.f;
                #pragma unroll
                for (int j = 0; j < 8; j++){ t1 += s_red[rl][j][0]; t2 += s_red[rl][j][1]; }
                float mean = t1 * (1.f/256.f);
                float var  = t2 * (1.f/256.f) - mean*mean;
                float rstd = rsqrtf(var + 1e-5f);
                int base = rl*264 + wn*32 + 2*q;
                #pragma unroll
                for (int f = 0; f < 4; f++){
                    float2 hv;
                    hv.x = to_tf32((acc[g][f][2*h]   - mean) * rstd);
                    hv.y = to_tf32((acc[g][f][2*h+1] - mean) * rstd);
                    *(float2*)(P + base + f*8) = hv;
                }
            }
    } else {
        #pragma unroll
        for (int g = 0; g < 2; g++)
            #pragma unroll
            for (int h = 0; h < 2; h++){
                int row = m0 + wm*32 + g*16 + h*8 + r4;
                float* op = outp + (size_t)row*N + n0 + wn*32 + 2*q;
                #pragma unroll
                for (int f = 0; f < 4; f++){
                    float2 o2; o2.x = acc[g][f][2*h]; o2.y = acc[g][f][2*h+1];
                    *(float2*)(op + f*8) = o2;
                }
            }
    }
    __syncthreads();
}

// ---------- einsum (single TF32 HMMA): partial[j][d] = sum_i A[b,i,j,r]*p_r[i][d] ----------
// M=64(j), K=64(i), N=256(d). p already tf32 in smem.
__device__ void einsum_mma(const float* __restrict__ A, int b, int r, char* dyn)
{
    const int t = threadIdx.x, w = t >> 5, lane = t & 31;
    const int wm = w & 1, wn = w >> 1;
    const int r4 = lane >> 2, q = lane & 3;

    float* As_e = (float*)(dyn + OFF_ASE);   // [64][68]
    float* P    = (float*)(dyn + OFF_BSM);   // [64][264]

    // stage A transposed (tf32): As[j][i] = A[b,i,j,r]
    const float* Ab = A + (size_t)b*32768 + r;
    #pragma unroll
    for (int pass = 0; pass < 8; pass++){
        int e = pass*512 + t;
        int j = e & 63, i = e >> 6;
        As_e[j*68 + i] = to_tf32(Ab[(size_t)i*512 + j*8]);
    }
    __syncthreads();

    float acc[2][4][4];
    #pragma unroll
    for (int g = 0; g < 2; g++)
        #pragma unroll
        for (int f = 0; f < 4; f++)
            #pragma unroll
            for (int rr = 0; rr < 4; rr++) acc[g][f][rr] = 0.f;

    const float* Abase = As_e + (wm*32 + r4)*68 + q;
    const float* Bbase = P + q*264 + wn*32 + r4;
    #pragma unroll
    for (int ks = 0; ks < 8; ks++){
        unsigned a[2][4], bfr[4][2];
        const float* Ak = Abase + ks*8;
        #pragma unroll
        for (int g = 0; g < 2; g++){
            const float* Ag = Ak + g*16*68;
            a[g][0] = __float_as_uint(Ag[0]);
            a[g][1] = __float_as_uint(Ag[8*68]);
            a[g][2] = __float_as_uint(Ag[4]);
            a[g][3] = __float_as_uint(Ag[8*68 + 4]);
        }
        const float* Bk = Bbase + ks*8*264;
        #pragma unroll
        for (int f = 0; f < 4; f++){
            bfr[f][0] = __float_as_uint(Bk[f*8]);
            bfr[f][1] = __float_as_uint(Bk[4*264 + f*8]);
        }
        #pragma unroll
        for (int g = 0; g < 2; g++)
            #pragma unroll
            for (int f = 0; f < 4; f++)
                mma_tf32(acc[g][f], a[g], bfr[f]);
    }

    // write partial to global
    float* pb = g_part + (size_t)(b*8 + r)*64*256;
    #pragma unroll
    for (int g = 0; g < 2; g++)
        #pragma unroll
        for (int h = 0; h < 2; h++){
            int j = wm*32 + g*16 + h*8 + r4;
            float* op = pb + (size_t)j*256 + wn*32 + 2*q;
            #pragma unroll
            for (int f = 0; f < 4; f++){
                float2 o2; o2.x = acc[g][f][2*h]; o2.y = acc[g][f][2*h+1];
                *(float2*)(op + f*8) = o2;
            }
        }
    __syncthreads();
}

// ---------- step phases 2+3 ----------
__device__ void step23(const float* __restrict__ Wout, const float* __restrict__ bout,
                       int iter, char* dyn)
{
    StepSm* sm = (StepSm*)dyn;
    const int t  = threadIdx.x;
    const int b  = blockIdx.x >> 3;
    const int j0 = (blockIdx.x & 7) * 8;
    const int row0 = b*64 + j0;
    const int w = t >> 5, lane = t & 31;

    // phase 2: ALL 16 warps; warp = (row r, d-half dh)
    {
        const int r  = w & 7;
        const int dh = w >> 3;
        const int j  = j0 + r;
        const float* iorow = g_io + (size_t)(row0 + r)*768;
        const float* pp = g_part + (size_t)(b*8)*64*256 + (size_t)j*256;
        float hv2[4];
        float s = 0.f, s2 = 0.f;
        #pragma unroll
        for (int qq = 0; qq < 4; qq++){
            int d = dh*128 + qq*32 + lane;
            float x = 0.f;
            #pragma unroll
            for (int rel = 0; rel < 8; rel++)
                x += pp[(size_t)rel*64*256 + d];
            x = x - tanhf(x);
            x += iorow[512 + d];
            hv2[qq] = x;
            s += x; s2 += x*x;
        }
        #pragma unroll
        for (int o = 16; o > 0; o >>= 1){
            s  += __shfl_xor_sync(0xffffffffu, s,  o);
            s2 += __shfl_xor_sync(0xffffffffu, s2, o);
        }
        if (lane == 0){ sm->lnp[r][dh][0] = s; sm->lnp[r][dh][1] = s2; }
        __syncthreads();
        float t1 = sm->lnp[r][0][0] + sm->lnp[r][1][0];
        float t2 = sm->lnp[r][0][1] + sm->lnp[r][1][1];
        float mean = t1 * (1.f/256.f);
        float var  = t2 * (1.f/256.f) - mean*mean;
        float rstd = rsqrtf(var + 1e-5f);
        #pragma unroll
        for (int qq = 0; qq < 4; qq++){
            int d = dh*128 + qq*32 + lane;
            float lnv = (hv2[qq]-mean)*rstd;
            float g = fmaf(iorow[d], lnv, iorow[256+d]);
            sm->hsm[d][r] = fmaxf(g, 0.f);
        }
    }
    __syncthreads();

    // phase 3: y = tanh(h @ Wout + b); k split across thread halves, coalesced Wout
    const int n    = t & 255;
    const int half = t >> 8;
    ull yacc[4] = {0ull, 0ull, 0ull, 0ull};
    const float* wcol = Wout + (size_t)half*128*256 + n;
    #pragma unroll 4
    for (int k = 0; k < 128; k++){
        ull w2 = pack2(wcol[(size_t)k*256]);
        ulonglong2 h01 = *(const ulonglong2*)&sm->hsm[half*128 + k][0];
        ulonglong2 h23 = *(const ulonglong2*)&sm->hsm[half*128 + k][4];
        ffma2(yacc[0], h01.x, w2);
        ffma2(yacc[1], h01.y, w2);
        ffma2(yacc[2], h23.x, w2);
        ffma2(yacc[3], h23.y, w2);
    }
    if (half == 0){
        sm->red[n][0] = yacc[0]; sm->red[n][1] = yacc[1];
        sm->red[n][2] = yacc[2]; sm->red[n][3] = yacc[3];
    }
    __syncthreads();
    if (half == 1){
        float bo = bout[n];
        bool masked = (iter > g_len[b]);
        #pragma unroll
        for (int q2 = 0; q2 < 4; q2++){
            float2 u = unpack2(yacc[q2]);
            float2 v = unpack2(sm->red[n][q2]);
            float y0 = masked ? 0.f : to_tf32(tanhf(u.x + v.x + bo));
            float y1 = masked ? 0.f : to_tf32(tanhf(u.y + v.y + bo));
            g_h[(size_t)(row0 + 2*q2    )*256 + n] = y0;
            g_h[(size_t)(row0 + 2*q2 + 1)*256 + n] = y1;
        }
    }
    __syncthreads();
}

// ---------- single persistent kernel ----------
__global__ void __launch_bounds__(512) fused_kernel(
    const int* __restrict__ tokens, const float* __restrict__ A,
    const float* __restrict__ root, const float* __restrict__ emb,
    const float* __restrict__ Wp,   const float* __restrict__ bp,
    const float* __restrict__ Win,  const float* __restrict__ bin,
    const float* __restrict__ Wout, const float* __restrict__ bout,
    float* __restrict__ out)
{
    extern __shared__ char smraw[];
    char* dyn = (char*)((((size_t)smraw) + 1023) & ~(size_t)1023);
    __shared__ float s_red[64][8][2];

    const int bid = blockIdx.x;
    const int t = threadIdx.x;
    const int b = bid >> 3, r = bid & 7;

    // prologue
    {
        int idx = r*512 + t;
        int l = idx >> 6;
        int c4 = (idx & 63) * 4;
        int row = b*64 + l;
        int tok = tokens[l*16 + b];
        float4 e4 = *(const float4*)&emb[(size_t)tok*256 + c4];
        e4.x = to_tf32(e4.x); e4.y = to_tf32(e4.y); e4.z = to_tf32(e4.z); e4.w = to_tf32(e4.w);
        *(float4*)&g_x[(size_t)row*256 + c4] = e4;
        float4 z; z.x=z.y=z.z=z.w=0.f;
        *(float4*)&g_h[(size_t)row*256 + c4] = z;
        if (r == 0 && t == 0){
            int c = 0;
            for (int l2 = 0; l2 < 64; l2++) c += (tokens[l2*16 + b] != 0);
            g_len[b] = c;
        }
        int gidx = bid*512 + t;
        #pragma unroll
        for (int i = 0; i < 2; i++){
            int e = gidx + i*65536;
            float4 v = *(const float4*)&Wp[(size_t)e*4];
            v.x = to_tf32(v.x); v.y = to_tf32(v.y); v.z = to_tf32(v.z); v.w = to_tf32(v.w);
            *(float4*)&g_wpR[(size_t)e*4] = v;
        }
        if (gidx < 49152){
            float4 v = *(const float4*)&Win[(size_t)gidx*4];
            v.x = to_tf32(v.x); v.y = to_tf32(v.y); v.z = to_tf32(v.z); v.w = to_tf32(v.w);
            *(float4*)&g_winR[(size_t)gidx*4] = v;
        }
    }
    grid_sync();

    // hoisted in_proj (blocks r<3 cover N=768)
    if (r < 3)
        gemm_mma(g_x, g_winR, bin, g_io, 768, b*64, r*256, 0, dyn, s_red);
    group_sync(b);

    // 64-step recurrence — batch-local
    for (int it = 0; it < 64; it++){
        gemm_mma(g_h, g_wpR, bp, (float*)0, 2048, b*64, r*256, 1, dyn, s_red);
        einsum_mma(A, b, r, dyn);
        group_sync(b);
        step23(Wout, bout, 64 - it, dyn);
        group_sync(b);
    }

    // epilogue
    if (r == 0 && t < 256){
        float s = 0.f;
        #pragma unroll 8
        for (int i = 0; i < 64; i++)
            s += g_h[(size_t)(b*64 + i)*256 + t] * root[b*64 + i];
        out[b*256 + t] = s;
    }
}

extern "C" void kernel_launch(void* const* d_in, const int* in_sizes, int n_in,
                              void* d_out, int out_size)
{
    const int*   tokens = (const int*)  d_in[0];
    const float* A      = (const float*)d_in[1];
    const float* root   = (const float*)d_in[2];
    const float* emb    = (const float*)d_in[3];
    const float* Wp     = (const float*)d_in[4];
    const float* bp     = (const float*)d_in[5];
    const float* Win    = (const float*)d_in[6];
    const float* bin    = (const float*)d_in[7];
    const float* Wout   = (const float*)d_in[8];
    const float* bout   = (const float*)d_in[9];

    cudaFuncSetAttribute(fused_kernel, cudaFuncAttributeMaxDynamicSharedMemorySize, SMEM_DYN);
    fused_kernel<<<NBLOCKS, 512, SMEM_DYN>>>(tokens, A, root, emb, Wp, bp, Win, bin,
                                             Wout, bout, (float*)d_out);
}

// round 12
// speedup vs baseline: 2.1143x; 1.2299x over previous
#include <cuda_runtime.h>
#include <cuda_fp16.h>

#define NBLOCKS 128
typedef unsigned long long ull;

__device__ __align__(16) __half g_xh [1024*256];     // gathered embeddings (half)
__device__ __align__(16) float  g_io [1024*768];     // shift|scale|proj_x (fp32)
__device__ __align__(16) float  g_part[16*8*64*256]; // [b][rel][j][d] partial lin_sum
__device__ __align__(16) __half g_hh [1024*256];     // recurrent state (half)
__device__ __align__(16) __half g_wpH [2048*256];    // Wp  transposed [n][k] half
__device__ __align__(16) __half g_winH[768*256];     // Win transposed [n][k] half
__device__ int g_len[16];
__device__ unsigned g_cnt = 0, g_gen = 0;
__device__ unsigned g_gcnt[16*32];
__device__ unsigned g_ggen[16*32];

// ---------- helpers ----------
__device__ __forceinline__ ull pack2(float v){
    ull r; asm("mov.b64 %0, {%1, %1};" : "=l"(r) : "f"(v)); return r;
}
__device__ __forceinline__ float2 unpack2(ull v){
    float2 r; asm("mov.b64 {%0, %1}, %2;" : "=f"(r.x), "=f"(r.y) : "l"(v)); return r;
}
__device__ __forceinline__ void ffma2(ull& d, ull a, ull b){
    asm("fma.rn.f32x2 %0, %1, %2, %0;" : "+l"(d) : "l"(a), "l"(b));
}
__device__ __forceinline__ void cpa16(void* s, const void* g){
    unsigned ss = (unsigned)__cvta_generic_to_shared(s);
    asm volatile("cp.async.cg.shared.global [%0], [%1], 16;\n" :: "r"(ss), "l"(g));
}
#define CPA_COMMIT() asm volatile("cp.async.commit_group;\n" ::: "memory")
#define CPA_WAIT0()  asm volatile("cp.async.wait_group 0;\n" ::: "memory")

// legacy HMMA m16n8k16 fp16, fp32 accumulate (base sm_103-legal)
__device__ __forceinline__ void mma_f16(float* d, const unsigned* a, const unsigned* b){
    asm volatile(
        "mma.sync.aligned.m16n8k16.row.col.f32.f16.f16.f32 "
        "{%0,%1,%2,%3}, {%4,%5,%6,%7}, {%8,%9}, {%0,%1,%2,%3};"
        : "+f"(d[0]), "+f"(d[1]), "+f"(d[2]), "+f"(d[3])
        : "r"(a[0]), "r"(a[1]), "r"(a[2]), "r"(a[3]), "r"(b[0]), "r"(b[1]));
}

// ---------- dynamic smem layout (bytes) ----------
// [0,10240)      gemm Asm half[2][64][40]      | StepSm (20.6KB, spills into Bsm)
// [10240,51200)  gemm Bsm half[2][256][40]     | P half[256][72] (36.9KB)
// [51200,60416)  AsE half[64][72] (persistent einsum A)
#define OFF_BSM 10240
#define OFF_ASE 51200
#define SMEM_DYN 62464
struct StepSm { float hsm[256][12]; ull red[256][4]; float lnp[8][2][2]; };

// ---------- barriers ----------
__device__ __forceinline__ void grid_sync(){
    __threadfence();
    __syncthreads();
    if (threadIdx.x == 0){
        unsigned my = *(volatile unsigned*)&g_gen;
        if (atomicAdd(&g_cnt, 1u) == NBLOCKS - 1u){
            g_cnt = 0;
            __threadfence();
            atomicAdd(&g_gen, 1u);
        } else {
            while (*(volatile unsigned*)&g_gen == my) __nanosleep(64);
        }
        __threadfence();
    }
    __syncthreads();
}

__device__ __forceinline__ void group_sync(int b){
    __threadfence();
    __syncthreads();
    if (threadIdx.x == 0){
        volatile unsigned* gen = &g_ggen[b*32];
        unsigned my = *gen;
        if (atomicAdd(&g_gcnt[b*32], 1u) == 7u){
            g_gcnt[b*32] = 0;
            __threadfence();
            atomicAdd((unsigned*)&g_ggen[b*32], 1u);
        } else {
            while (*gen == my) __nanosleep(32);
        }
        __threadfence();
    }
    __syncthreads();
}

// ---------- fp16 HMMA GEMM tile: 64(m) x 256(n), K=256, chunks of 32 ----------
// mode 0: +bias, STG fp32 to outp. mode 1: +bias, LN, STS half to P[d][i].
__device__ void gemm_mma(const __half* __restrict__ Asrc, const __half* __restrict__ BsrcT,
                         const float* __restrict__ bias, float* __restrict__ outp,
                         int N, int m0, int n0, int mode, char* dyn,
                         float (*s_red)[8][2])
{
    const int t = threadIdx.x, w = t >> 5, lane = t & 31;
    const int wm = w & 1, wn = w >> 1;
    const int r4 = lane >> 2, q = lane & 3;

    __half* Asm = (__half*)dyn;                // [2][64][40]
    __half* Bsm = (__half*)(dyn + OFF_BSM);    // [2][256][40]

    float acc[2][4][4];
    #pragma unroll
    for (int g = 0; g < 2; g++)
        #pragma unroll
        for (int f = 0; f < 4; f++)
            #pragma unroll
            for (int rr = 0; rr < 4; rr++) acc[g][f][rr] = 0.f;

    // chunk 0 staging
    if (t < 256){
        int am = t >> 2, ak8 = (t & 3) * 8;
        cpa16(Asm + am*40 + ak8, Asrc + (size_t)(m0 + am)*256 + ak8);
    }
    #pragma unroll
    for (int i = 0; i < 2; i++){
        int idx = t + i*512, bn = idx >> 2, bk8 = (idx & 3) * 8;
        cpa16(Bsm + bn*40 + bk8, BsrcT + (size_t)(n0 + bn)*256 + bk8);
    }
    CPA_COMMIT(); CPA_WAIT0();
    __syncthreads();

    for (int c = 0; c < 8; c++){
        const int buf = c & 1;
        if (c < 7){
            const int nb = buf ^ 1;
            if (t < 256){
                int am = t >> 2, ak8 = (t & 3) * 8;
                cpa16(Asm + nb*2560 + am*40 + ak8,
                      Asrc + (size_t)(m0 + am)*256 + (c+1)*32 + ak8);
            }
            #pragma unroll
            for (int i = 0; i < 2; i++){
                int idx = t + i*512, bn = idx >> 2, bk8 = (idx & 3) * 8;
                cpa16(Bsm + nb*10240 + bn*40 + bk8,
                      BsrcT + (size_t)(n0 + bn)*256 + (c+1)*32 + bk8);
            }
            CPA_COMMIT();
        }
        const __half* Ab = Asm + buf*2560  + (wm*32 + r4)*40 + 2*q;
        const __half* Bb = Bsm + buf*10240 + (wn*32 + r4)*40 + 2*q;
        #pragma unroll
        for (int ks = 0; ks < 2; ks++){
            const int kb = ks*16;
            unsigned a[2][4], bf[4][2];
            #pragma unroll
            for (int g = 0; g < 2; g++){
                const __half* Ag = Ab + g*16*40 + kb;
                a[g][0] = *(const unsigned*)(Ag);
                a[g][1] = *(const unsigned*)(Ag + 320);
                a[g][2] = *(const unsigned*)(Ag + 8);
                a[g][3] = *(const unsigned*)(Ag + 328);
            }
            #pragma unroll
            for (int f = 0; f < 4; f++){
                const __half* Bf = Bb + f*8*40 + kb;
                bf[f][0] = *(const unsigned*)(Bf);
                bf[f][1] = *(const unsigned*)(Bf + 8);
            }
            #pragma unroll
            for (int g = 0; g < 2; g++)
                #pragma unroll
                for (int f = 0; f < 4; f++)
                    mma_f16(acc[g][f], a[g], bf[f]);
        }
        if (c < 7) CPA_WAIT0();
        __syncthreads();
    }

    #pragma unroll
    for (int f = 0; f < 4; f++){
        float b0 = bias[n0 + wn*32 + f*8 + 2*q];
        float b1 = bias[n0 + wn*32 + f*8 + 2*q + 1];
        #pragma unroll
        for (int g = 0; g < 2; g++){
            acc[g][f][0] += b0; acc[g][f][1] += b1;
            acc[g][f][2] += b0; acc[g][f][3] += b1;
        }
    }

    if (mode == 1){
        #pragma unroll
        for (int g = 0; g < 2; g++)
            #pragma unroll
            for (int h = 0; h < 2; h++){
                float s1 = 0.f, s2 = 0.f;
                #pragma unroll
                for (int f = 0; f < 4; f++){
                    float v0 = acc[g][f][2*h], v1 = acc[g][f][2*h + 1];
                    s1 += v0 + v1; s2 += v0*v0 + v1*v1;
                }
                s1 += __shfl_xor_sync(0xffffffffu, s1, 1);
                s2 += __shfl_xor_sync(0xffffffffu, s2, 1);
                s1 += __shfl_xor_sync(0xffffffffu, s1, 2);
                s2 += __shfl_xor_sync(0xffffffffu, s2, 2);
                if (q == 0){
                    int rl = wm*32 + g*16 + h*8 + r4;
                    s_red[rl][wn][0] = s1; s_red[rl][wn][1] = s2;
                }
            }
        __syncthreads();
        __half* P = (__half*)(dyn + OFF_BSM);    // [256 d][72 i]
        #pragma unroll
        for (int g = 0; g < 2; g++)
            #pragma unroll
            for (int h = 0; h < 2; h++){
                int rl = wm*32 + g*16 + h*8 + r4;
                float t1 = 0.f, t2 = 0.f;
                #pragma unroll
                for (int j = 0; j < 8; j++){ t1 += s_red[rl][j][0]; t2 += s_red[rl][j][1]; }
                float mean = t1 * (1.f/256.f);
                float var  = t2 * (1.f/256.f) - mean*mean;
                float rstd = rsqrtf(var + 1e-5f);
                #pragma unroll
                for (int f = 0; f < 4; f++){
                    float v0 = (acc[g][f][2*h]   - mean) * rstd;
                    float v1 = (acc[g][f][2*h+1] - mean) * rstd;
                    int colb = wn*32 + f*8 + 2*q;
                    P[(size_t)(colb  )*72 + rl] = __float2half(v0);
                    P[(size_t)(colb+1)*72 + rl] = __float2half(v1);
                }
            }
    } else {
        #pragma unroll
        for (int g = 0; g < 2; g++)
            #pragma unroll
            for (int h = 0; h < 2; h++){
                int row = m0 + wm*32 + g*16 + h*8 + r4;
                float* op = outp + (size_t)row*N + n0 + wn*32 + 2*q;
                #pragma unroll
                for (int f = 0; f < 4; f++){
                    float2 o2; o2.x = acc[g][f][2*h]; o2.y = acc[g][f][2*h+1];
                    *(float2*)(op + f*8) = o2;
                }
            }
    }
    __syncthreads();
}

// ---------- einsum A staging (once; A is loop-invariant) ----------
__device__ void stage_Ae(const float* __restrict__ A, int b, int r, char* dyn){
    __half* AsE = (__half*)(dyn + OFF_ASE);   // [64 j][72 i]
    const float* Ab = A + (size_t)b*32768 + r;
    const int t = threadIdx.x;
    #pragma unroll
    for (int pass = 0; pass < 8; pass++){
        int e = pass*512 + t;
        int j = e & 63, i = e >> 6;
        AsE[j*72 + i] = __float2half(Ab[(size_t)i*512 + j*8]);
    }
    __syncthreads();
}

// ---------- einsum (fp16 HMMA): partial[j][d] = sum_i A[b,i,j,r]*p_r[i][d] ----------
// M=64(j), K=64(i), N=256(d); A in AsE[j][i], p in P[d][i] (both half, in smem)
__device__ void einsum_mma(int b, int r, char* dyn)
{
    const int t = threadIdx.x, w = t >> 5, lane = t & 31;
    const int wm = w & 1, wn = w >> 1;
    const int r4 = lane >> 2, q = lane & 3;

    const __half* AsE = (const __half*)(dyn + OFF_ASE);
    const __half* P   = (const __half*)(dyn + OFF_BSM);

    float acc[2][4][4];
    #pragma unroll
    for (int g = 0; g < 2; g++)
        #pragma unroll
        for (int f = 0; f < 4; f++)
            #pragma unroll
            for (int rr = 0; rr < 4; rr++) acc[g][f][rr] = 0.f;

    const __half* Ab = AsE + (wm*32 + r4)*72 + 2*q;
    const __half* Bb = P   + (wn*32 + r4)*72 + 2*q;
    #pragma unroll
    for (int ks = 0; ks < 4; ks++){
        const int kb = ks*16;
        unsigned a[2][4], bf[4][2];
        #pragma unroll
        for (int g = 0; g < 2; g++){
            const __half* Ag = Ab + g*16*72 + kb;
            a[g][0] = *(const unsigned*)(Ag);
            a[g][1] = *(const unsigned*)(Ag + 576);
            a[g][2] = *(const unsigned*)(Ag + 8);
            a[g][3] = *(const unsigned*)(Ag + 584);
        }
        #pragma unroll
        for (int f = 0; f < 4; f++){
            const __half* Bf = Bb + f*8*72 + kb;
            bf[f][0] = *(const unsigned*)(Bf);
            bf[f][1] = *(const unsigned*)(Bf + 8);
        }
        #pragma unroll
        for (int g = 0; g < 2; g++)
            #pragma unroll
            for (int f = 0; f < 4; f++)
                mma_f16(acc[g][f], a[g], bf[f]);
    }

    float* pb = g_part + (size_t)(b*8 + r)*64*256;
    #pragma unroll
    for (int g = 0; g < 2; g++)
        #pragma unroll
        for (int h = 0; h < 2; h++){
            int j = wm*32 + g*16 + h*8 + r4;
            float* op = pb + (size_t)j*256 + wn*32 + 2*q;
            #pragma unroll
            for (int f = 0; f < 4; f++){
                float2 o2; o2.x = acc[g][f][2*h]; o2.y = acc[g][f][2*h+1];
                *(float2*)(op + f*8) = o2;
            }
        }
    __syncthreads();
}

// ---------- step phases 2+3 ----------
__device__ void step23(const float* __restrict__ Wout, const float* __restrict__ bout,
                       int iter, char* dyn)
{
    StepSm* sm = (StepSm*)dyn;
    const int t  = threadIdx.x;
    const int b  = blockIdx.x >> 3;
    const int j0 = (blockIdx.x & 7) * 8;
    const int row0 = b*64 + j0;
    const int w = t >> 5, lane = t & 31;

    // phase 2: 16 warps; warp = (row r, d-half dh)
    {
        const int r  = w & 7;
        const int dh = w >> 3;
        const int j  = j0 + r;
        const float* iorow = g_io + (size_t)(row0 + r)*768;
        const float* pp = g_part + (size_t)(b*8)*64*256 + (size_t)j*256;
        float hv2[4];
        float s = 0.f, s2 = 0.f;
        #pragma unroll
        for (int qq = 0; qq < 4; qq++){
            int d = dh*128 + qq*32 + lane;
            float x = 0.f;
            #pragma unroll
            for (int rel = 0; rel < 8; rel++)
                x += pp[(size_t)rel*64*256 + d];
            x = x - tanhf(x);
            x += iorow[512 + d];
            hv2[qq] = x;
            s += x; s2 += x*x;
        }
        #pragma unroll
        for (int o = 16; o > 0; o >>= 1){
            s  += __shfl_xor_sync(0xffffffffu, s,  o);
            s2 += __shfl_xor_sync(0xffffffffu, s2, o);
        }
        if (lane == 0){ sm->lnp[r][dh][0] = s; sm->lnp[r][dh][1] = s2; }
        __syncthreads();
        float t1 = sm->lnp[r][0][0] + sm->lnp[r][1][0];
        float t2 = sm->lnp[r][0][1] + sm->lnp[r][1][1];
        float mean = t1 * (1.f/256.f);
        float var  = t2 * (1.f/256.f) - mean*mean;
        float rstd = rsqrtf(var + 1e-5f);
        #pragma unroll
        for (int qq = 0; qq < 4; qq++){
            int d = dh*128 + qq*32 + lane;
            float lnv = (hv2[qq]-mean)*rstd;
            float g = fmaf(iorow[d], lnv, iorow[256+d]);
            sm->hsm[d][r] = fmaxf(g, 0.f);
        }
    }
    __syncthreads();

    // phase 3: y = tanh(h @ Wout + b); k split across thread halves, coalesced Wout
    const int n    = t & 255;
    const int half = t >> 8;
    ull yacc[4] = {0ull, 0ull, 0ull, 0ull};
    const float* wcol = Wout + (size_t)half*128*256 + n;
    #pragma unroll 4
    for (int k = 0; k < 128; k++){
        ull w2 = pack2(wcol[(size_t)k*256]);
        ulonglong2 h01 = *(const ulonglong2*)&sm->hsm[half*128 + k][0];
        ulonglong2 h23 = *(const ulonglong2*)&sm->hsm[half*128 + k][4];
        ffma2(yacc[0], h01.x, w2);
        ffma2(yacc[1], h01.y, w2);
        ffma2(yacc[2], h23.x, w2);
        ffma2(yacc[3], h23.y, w2);
    }
    if (half == 0){
        sm->red[n][0] = yacc[0]; sm->red[n][1] = yacc[1];
        sm->red[n][2] = yacc[2]; sm->red[n][3] = yacc[3];
    }
    __syncthreads();
    if (half == 1){
        float bo = bout[n];
        bool masked = (iter > g_len[b]);
        #pragma unroll
        for (int q2 = 0; q2 < 4; q2++){
            float2 u = unpack2(yacc[q2]);
            float2 v = unpack2(sm->red[n][q2]);
            float y0 = masked ? 0.f : tanhf(u.x + v.x + bo);
            float y1 = masked ? 0.f : tanhf(u.y + v.y + bo);
            g_hh[(size_t)(row0 + 2*q2    )*256 + n] = __float2half(y0);
            g_hh[(size_t)(row0 + 2*q2 + 1)*256 + n] = __float2half(y1);
        }
    }
    __syncthreads();
}

// ---------- 64x64 weight tile transpose fp32 -> [n][k] half ----------
__device__ void transpose_w(const float* __restrict__ src, __half* __restrict__ dst,
                            int Nn, int tk, int tn, char* dyn)
{
    float (*ts)[65] = (float(*)[65])dyn;
    const int t = threadIdx.x;
    const int rr = t >> 6, cc = t & 63;
    #pragma unroll
    for (int pass = 0; pass < 8; pass++){
        int r = pass*8 + rr;
        ts[r][cc] = src[(size_t)(tk*64 + r)*Nn + tn*64 + cc];
    }
    __syncthreads();
    #pragma unroll
    for (int pass = 0; pass < 8; pass++){
        int r = pass*8 + rr;
        dst[(size_t)(tn*64 + r)*256 + tk*64 + cc] = __float2half(ts[cc][r]);
    }
    __syncthreads();
}

// ---------- single persistent kernel ----------
__global__ void __launch_bounds__(512) fused_kernel(
    const int* __restrict__ tokens, const float* __restrict__ A,
    const float* __restrict__ root, const float* __restrict__ emb,
    const float* __restrict__ Wp,   const float* __restrict__ bp,
    const float* __restrict__ Win,  const float* __restrict__ bin,
    const float* __restrict__ Wout, const float* __restrict__ bout,
    float* __restrict__ out)
{
    extern __shared__ char smraw[];
    char* dyn = (char*)((((size_t)smraw) + 1023) & ~(size_t)1023);
    __shared__ float s_red[64][8][2];

    const int bid = blockIdx.x;
    const int t = threadIdx.x;
    const int b = bid >> 3, r = bid & 7;

    // prologue: gather (half), zero h, lengths, weight transposes
    {
        int idx = r*512 + t;
        int l = idx >> 6;
        int c4 = (idx & 63) * 4;
        int row = b*64 + l;
        int tok = tokens[l*16 + b];
        float4 e4 = *(const float4*)&emb[(size_t)tok*256 + c4];
        __half2 h0 = __floats2half2_rn(e4.x, e4.y);
        __half2 h1 = __floats2half2_rn(e4.z, e4.w);
        uint2 u; u.x = *(unsigned*)&h0; u.y = *(unsigned*)&h1;
        *(uint2*)&g_xh[(size_t)row*256 + c4] = u;
        uint2 z; z.x = 0u; z.y = 0u;
        *(uint2*)&g_hh[(size_t)row*256 + c4] = z;
        if (r == 0 && t == 0){
            int c = 0;
            for (int l2 = 0; l2 < 64; l2++) c += (tokens[l2*16 + b] != 0);
            g_len[b] = c;
        }
    }
    // Wp: 256x2048 -> wpH [2048][256]; 128 tiles of 64x64, one per block
    transpose_w(Wp, g_wpH, 2048, bid >> 5, bid & 31, dyn);
    // Win: 256x768 -> winH [768][256]; 48 tiles, blocks 0..47
    if (bid < 48)
        transpose_w(Win, g_winH, 768, bid / 12, bid % 12, dyn);
    grid_sync();

    // stage einsum A (loop-invariant) into persistent smem
    stage_Ae(A, b, r, dyn);

    // hoisted in_proj (blocks r<3 cover N=768)
    if (r < 3)
        gemm_mma(g_xh, g_winH, bin, g_io, 768, b*64, r*256, 0, dyn, s_red);
    group_sync(b);

    // 64-step recurrence — batch-local
    for (int it = 0; it < 64; it++){
        gemm_mma(g_hh, g_wpH, bp, (float*)0, 2048, b*64, r*256, 1, dyn, s_red);
        einsum_mma(b, r, dyn);
        group_sync(b);
        step23(Wout, bout, 64 - it, dyn);
        group_sync(b);
    }

    // epilogue: out[b][d] = sum_i h[b,i,d] * root[b,i]
    if (r == 0 && t < 256){
        float s = 0.f;
        #pragma unroll 8
        for (int i = 0; i < 64; i++)
            s += __half2float(g_hh[(size_t)(b*64 + i)*256 + t]) * root[b*64 + i];
        out[b*256 + t] = s;
    }
}

extern "C" void kernel_launch(void* const* d_in, const int* in_sizes, int n_in,
                              void* d_out, int out_size)
{
    const int*   tokens = (const int*)  d_in[0];
    const float* A      = (const float*)d_in[1];
    const float* root   = (const float*)d_in[2];
    const float* emb    = (const float*)d_in[3];
    const float* Wp     = (const float*)d_in[4];
    const float* bp     = (const float*)d_in[5];
    const float* Win    = (const float*)d_in[6];
    const float* bin    = (const float*)d_in[7];
    const float* Wout   = (const float*)d_in[8];
    const float* bout   = (const float*)d_in[9];

    cudaFuncSetAttribute(fused_kernel, cudaFuncAttributeMaxDynamicSharedMemorySize, SMEM_DYN);
    fused_kernel<<<NBLOCKS, 512, SMEM_DYN>>>(tokens, A, root, emb, Wp, bp, Win, bin,
                                             Wout, bout, (float*)d_out);
}

// round 13
// speedup vs baseline: 2.2819x; 1.0792x over previous
#include <cuda_runtime.h>
#include <cuda_fp16.h>

#define NBLOCKS 128
typedef unsigned long long ull;

__device__ __align__(16) __half g_xh [1024*256];     // gathered embeddings (half)
__device__ __align__(16) float  g_io [1024*768];     // shift|scale|proj_x (fp32)
__device__ __align__(16) float  g_part[16*8*64*256]; // [b][rel][j][d] partial lin_sum
__device__ __align__(16) __half g_hh [1024*256];     // recurrent state (half)
__device__ __align__(16) __half g_wpH [2048*256];    // Wp  transposed [n][k] half
__device__ __align__(16) __half g_winH[768*256];     // Win transposed [n][k] half
__device__ int g_len[16];
__device__ unsigned g_cnt = 0, g_gen = 0;
__device__ unsigned g_gcnt[16*32];
__device__ unsigned g_ggen[16*32];

// ---------- helpers ----------
__device__ __forceinline__ ull pack2(float v){
    ull r; asm("mov.b64 %0, {%1, %1};" : "=l"(r) : "f"(v)); return r;
}
__device__ __forceinline__ float2 unpack2(ull v){
    float2 r; asm("mov.b64 {%0, %1}, %2;" : "=f"(r.x), "=f"(r.y) : "l"(v)); return r;
}
__device__ __forceinline__ void ffma2(ull& d, ull a, ull b){
    asm("fma.rn.f32x2 %0, %1, %2, %0;" : "+l"(d) : "l"(a), "l"(b));
}
__device__ __forceinline__ void cpa16(void* s, const void* g){
    unsigned ss = (unsigned)__cvta_generic_to_shared(s);
    asm volatile("cp.async.cg.shared.global [%0], [%1], 16;\n" :: "r"(ss), "l"(g));
}
#define CPA_COMMIT() asm volatile("cp.async.commit_group;\n" ::: "memory")
#define CPA_WAIT0()  asm volatile("cp.async.wait_group 0;\n" ::: "memory")

// legacy HMMA m16n8k16 fp16, fp32 accumulate (base sm_103-legal)
__device__ __forceinline__ void mma_f16(float* d, const unsigned* a, const unsigned* b){
    asm volatile(
        "mma.sync.aligned.m16n8k16.row.col.f32.f16.f16.f32 "
        "{%0,%1,%2,%3}, {%4,%5,%6,%7}, {%8,%9}, {%0,%1,%2,%3};"
        : "+f"(d[0]), "+f"(d[1]), "+f"(d[2]), "+f"(d[3])
        : "r"(a[0]), "r"(a[1]), "r"(a[2]), "r"(a[3]), "r"(b[0]), "r"(b[1]));
}

// ---------- dynamic smem layout (bytes) ----------
// [0,135168)        B persistent half[256 n][264 k]   (Wp slice; Win slice during in_proj)
// [135168,168960)   A tile half[64 m][264 k]  | StepSm (20.6KB)
// [168960,205824)   P half[256 d][72 i]
// [205824,215040)   AsE half[64 j][72 i]  (persistent einsum A)
#define OFF_A    135168
#define OFF_P    168960
#define OFF_ASE  205824
#define SMEM_DYN 215040
struct StepSm { float hsm[256][12]; ull red[256][4]; float lnp[8][2][2]; };

// ---------- barriers ----------
__device__ __forceinline__ void grid_sync(){
    __threadfence();
    __syncthreads();
    if (threadIdx.x == 0){
        unsigned my = *(volatile unsigned*)&g_gen;
        if (atomicAdd(&g_cnt, 1u) == NBLOCKS - 1u){
            g_cnt = 0;
            __threadfence();
            atomicAdd(&g_gen, 1u);
        } else {
            while (*(volatile unsigned*)&g_gen == my) __nanosleep(64);
        }
        __threadfence();
    }
    __syncthreads();
}

__device__ __forceinline__ void group_sync(int b){
    __threadfence();
    __syncthreads();
    if (threadIdx.x == 0){
        volatile unsigned* gen = &g_ggen[b*32];
        unsigned my = *gen;
        if (atomicAdd(&g_gcnt[b*32], 1u) == 7u){
            g_gcnt[b*32] = 0;
            __threadfence();
            atomicAdd((unsigned*)&g_ggen[b*32], 1u);
        } else {
            while (*gen == my) __nanosleep(32);
        }
        __threadfence();
    }
    __syncthreads();
}

// ---------- stage persistent B slice (256 n x 256 k half) into smem ----------
__device__ void stage_B(const __half* __restrict__ BsrcT, int n0, char* dyn){
    __half* Bsm = (__half*)dyn;
    const int t = threadIdx.x;
    #pragma unroll
    for (int i = 0; i < 16; i++){
        int idx = t + i*512;                  // 0..8191
        int row = idx >> 5, col8 = (idx & 31)*8;
        cpa16(Bsm + row*264 + col8, BsrcT + (size_t)(n0 + row)*256 + col8);
    }
    CPA_COMMIT(); CPA_WAIT0();
    __syncthreads();
}

// ---------- fp16 HMMA GEMM tile: 64(m) x 256(n), K=256; B persistent in smem ----------
// mode 0: +bias, STG fp32 to outp. mode 1: +bias, LN, STS half to P[d][i].
__device__ void gemm_mma(const __half* __restrict__ Asrc,
                         const float* __restrict__ bias, float* __restrict__ outp,
                         int N, int m0, int n0, int mode, char* dyn,
                         float (*s_red)[8][2])
{
    const int t = threadIdx.x, w = t >> 5, lane = t & 31;
    const int wm = w & 1, wn = w >> 1;
    const int r4 = lane >> 2, q = lane & 3;

    __half* Asm = (__half*)(dyn + OFF_A);        // [64][264]
    const __half* Bsm = (const __half*)dyn;      // [256][264] persistent

    // stage full A tile (32 KB)
    #pragma unroll
    for (int i = 0; i < 4; i++){
        int idx = t + i*512;                  // 0..2047
        int row = idx >> 5, col8 = (idx & 31)*8;
        cpa16(Asm + row*264 + col8, Asrc + (size_t)(m0 + row)*256 + col8);
    }
    CPA_COMMIT(); CPA_WAIT0();
    __syncthreads();

    float acc[2][4][4];
    #pragma unroll
    for (int g = 0; g < 2; g++)
        #pragma unroll
        for (int f = 0; f < 4; f++)
            #pragma unroll
            for (int rr = 0; rr < 4; rr++) acc[g][f][rr] = 0.f;

    const __half* Ab = Asm + (wm*32 + r4)*264 + 2*q;
    const __half* Bb = Bsm + (wn*32 + r4)*264 + 2*q;
    #pragma unroll 4
    for (int ks = 0; ks < 16; ks++){
        const int kb = ks*16;
        unsigned a[2][4], bf[4][2];
        #pragma unroll
        for (int g = 0; g < 2; g++){
            const __half* Ag = Ab + g*16*264 + kb;
            a[g][0] = *(const unsigned*)(Ag);
            a[g][1] = *(const unsigned*)(Ag + 8*264);
            a[g][2] = *(const unsigned*)(Ag + 8);
            a[g][3] = *(const unsigned*)(Ag + 8*264 + 8);
        }
        #pragma unroll
        for (int f = 0; f < 4; f++){
            const __half* Bf = Bb + f*8*264 + kb;
            bf[f][0] = *(const unsigned*)(Bf);
            bf[f][1] = *(const unsigned*)(Bf + 8);
        }
        #pragma unroll
        for (int g = 0; g < 2; g++)
            #pragma unroll
            for (int f = 0; f < 4; f++)
                mma_f16(acc[g][f], a[g], bf[f]);
    }

    #pragma unroll
    for (int f = 0; f < 4; f++){
        float b0 = bias[n0 + wn*32 + f*8 + 2*q];
        float b1 = bias[n0 + wn*32 + f*8 + 2*q + 1];
        #pragma unroll
        for (int g = 0; g < 2; g++){
            acc[g][f][0] += b0; acc[g][f][1] += b1;
            acc[g][f][2] += b0; acc[g][f][3] += b1;
        }
    }

    if (mode == 1){
        #pragma unroll
        for (int g = 0; g < 2; g++)
            #pragma unroll
            for (int h = 0; h < 2; h++){
                float s1 = 0.f, s2 = 0.f;
                #pragma unroll
                for (int f = 0; f < 4; f++){
                    float v0 = acc[g][f][2*h], v1 = acc[g][f][2*h + 1];
                    s1 += v0 + v1; s2 += v0*v0 + v1*v1;
                }
                s1 += __shfl_xor_sync(0xffffffffu, s1, 1);
                s2 += __shfl_xor_sync(0xffffffffu, s2, 1);
                s1 += __shfl_xor_sync(0xffffffffu, s1, 2);
                s2 += __shfl_xor_sync(0xffffffffu, s2, 2);
                if (q == 0){
                    int rl = wm*32 + g*16 + h*8 + r4;
                    s_red[rl][wn][0] = s1; s_red[rl][wn][1] = s2;
                }
            }
        __syncthreads();
        __half* P = (__half*)(dyn + OFF_P);    // [256 d][72 i]
        #pragma unroll
        for (int g = 0; g < 2; g++)
            #pragma unroll
            for (int h = 0; h < 2; h++){
                int rl = wm*32 + g*16 + h*8 + r4;
                float t1 = 0.f, t2 = 0.f;
                #pragma unroll
                for (int j = 0; j < 8; j++){ t1 += s_red[rl][j][0]; t2 += s_red[rl][j][1]; }
                float mean = t1 * (1.f/256.f);
                float var  = t2 * (1.f/256.f) - mean*mean;
                float rstd = rsqrtf(var + 1e-5f);
                #pragma unroll
                for (int f = 0; f < 4; f++){
                    float v0 = (acc[g][f][2*h]   - mean) * rstd;
                    float v1 = (acc[g][f][2*h+1] - mean) * rstd;
                    int colb = wn*32 + f*8 + 2*q;
                    P[(size_t)(colb  )*72 + rl] = __float2half(v0);
                    P[(size_t)(colb+1)*72 + rl] = __float2half(v1);
                }
            }
    } else {
        #pragma unroll
        for (int g = 0; g < 2; g++)
            #pragma unroll
            for (int h = 0; h < 2; h++){
                int row = m0 + wm*32 + g*16 + h*8 + r4;
                float* op = outp + (size_t)row*N + n0 + wn*32 + 2*q;
                #pragma unroll
                for (int f = 0; f < 4; f++){
                    float2 o2; o2.x = acc[g][f][2*h]; o2.y = acc[g][f][2*h+1];
                    *(float2*)(op + f*8) = o2;
                }
            }
    }
    __syncthreads();
}

// ---------- einsum A staging (once; loop-invariant) ----------
__device__ void stage_Ae(const float* __restrict__ A, int b, int r, char* dyn){
    __half* AsE = (__half*)(dyn + OFF_ASE);   // [64 j][72 i]
    const float* Ab = A + (size_t)b*32768 + r;
    const int t = threadIdx.x;
    #pragma unroll
    for (int pass = 0; pass < 8; pass++){
        int e = pass*512 + t;
        int j = e & 63, i = e >> 6;
        AsE[j*72 + i] = __float2half(Ab[(size_t)i*512 + j*8]);
    }
    __syncthreads();
}

// ---------- einsum (fp16 HMMA): partial[j][d] = sum_i A[b,i,j,r]*p_r[i][d] ----------
__device__ void einsum_mma(int b, int r, char* dyn)
{
    const int t = threadIdx.x, w = t >> 5, lane = t & 31;
    const int wm = w & 1, wn = w >> 1;
    const int r4 = lane >> 2, q = lane & 3;

    const __half* AsE = (const __half*)(dyn + OFF_ASE);
    const __half* P   = (const __half*)(dyn + OFF_P);

    float acc[2][4][4];
    #pragma unroll
    for (int g = 0; g < 2; g++)
        #pragma unroll
        for (int f = 0; f < 4; f++)
            #pragma unroll
            for (int rr = 0; rr < 4; rr++) acc[g][f][rr] = 0.f;

    const __half* Ab = AsE + (wm*32 + r4)*72 + 2*q;
    const __half* Bb = P   + (wn*32 + r4)*72 + 2*q;
    #pragma unroll
    for (int ks = 0; ks < 4; ks++){
        const int kb = ks*16;
        unsigned a[2][4], bf[4][2];
        #pragma unroll
        for (int g = 0; g < 2; g++){
            const __half* Ag = Ab + g*16*72 + kb;
            a[g][0] = *(const unsigned*)(Ag);
            a[g][1] = *(const unsigned*)(Ag + 576);
            a[g][2] = *(const unsigned*)(Ag + 8);
            a[g][3] = *(const unsigned*)(Ag + 584);
        }
        #pragma unroll
        for (int f = 0; f < 4; f++){
            const __half* Bf = Bb + f*8*72 + kb;
            bf[f][0] = *(const unsigned*)(Bf);
            bf[f][1] = *(const unsigned*)(Bf + 8);
        }
        #pragma unroll
        for (int g = 0; g < 2; g++)
            #pragma unroll
            for (int f = 0; f < 4; f++)
                mma_f16(acc[g][f], a[g], bf[f]);
    }

    float* pb = g_part + (size_t)(b*8 + r)*64*256;
    #pragma unroll
    for (int g = 0; g < 2; g++)
        #pragma unroll
        for (int h = 0; h < 2; h++){
            int j = wm*32 + g*16 + h*8 + r4;
            float* op = pb + (size_t)j*256 + wn*32 + 2*q;
            #pragma unroll
            for (int f = 0; f < 4; f++){
                float2 o2; o2.x = acc[g][f][2*h]; o2.y = acc[g][f][2*h+1];
                *(float2*)(op + f*8) = o2;
            }
        }
    __syncthreads();
}

// ---------- step phases 2+3 ----------
__device__ void step23(const float* __restrict__ Wout, const float* __restrict__ bout,
                       int iter, char* dyn)
{
    StepSm* sm = (StepSm*)(dyn + OFF_A);
    const int t  = threadIdx.x;
    const int b  = blockIdx.x >> 3;
    const int j0 = (blockIdx.x & 7) * 8;
    const int row0 = b*64 + j0;
    const int w = t >> 5, lane = t & 31;

    // phase 2: 16 warps; warp = (row r, d-half dh)
    {
        const int r  = w & 7;
        const int dh = w >> 3;
        const int j  = j0 + r;
        const float* iorow = g_io + (size_t)(row0 + r)*768;
        const float* pp = g_part + (size_t)(b*8)*64*256 + (size_t)j*256;
        float hv2[4];
        float s = 0.f, s2 = 0.f;
        #pragma unroll
        for (int qq = 0; qq < 4; qq++){
            int d = dh*128 + qq*32 + lane;
            float x = 0.f;
            #pragma unroll
            for (int rel = 0; rel < 8; rel++)
                x += pp[(size_t)rel*64*256 + d];
            x = x - tanhf(x);
            x += iorow[512 + d];
            hv2[qq] = x;
            s += x; s2 += x*x;
        }
        #pragma unroll
        for (int o = 16; o > 0; o >>= 1){
            s  += __shfl_xor_sync(0xffffffffu, s,  o);
            s2 += __shfl_xor_sync(0xffffffffu, s2, o);
        }
        if (lane == 0){ sm->lnp[r][dh][0] = s; sm->lnp[r][dh][1] = s2; }
        __syncthreads();
        float t1 = sm->lnp[r][0][0] + sm->lnp[r][1][0];
        float t2 = sm->lnp[r][0][1] + sm->lnp[r][1][1];
        float mean = t1 * (1.f/256.f);
        float var  = t2 * (1.f/256.f) - mean*mean;
        float rstd = rsqrtf(var + 1e-5f);
        #pragma unroll
        for (int qq = 0; qq < 4; qq++){
            int d = dh*128 + qq*32 + lane;
            float lnv = (hv2[qq]-mean)*rstd;
            float g = fmaf(iorow[d], lnv, iorow[256+d]);
            sm->hsm[d][r] = fmaxf(g, 0.f);
        }
    }
    __syncthreads();

    // phase 3: y = tanh(h @ Wout + b); k split across thread halves, coalesced Wout
    const int n    = t & 255;
    const int half = t >> 8;
    ull yacc[4] = {0ull, 0ull, 0ull, 0ull};
    const float* wcol = Wout + (size_t)half*128*256 + n;
    #pragma unroll 4
    for (int k = 0; k < 128; k++){
        ull w2 = pack2(wcol[(size_t)k*256]);
        ulonglong2 h01 = *(const ulonglong2*)&sm->hsm[half*128 + k][0];
        ulonglong2 h23 = *(const ulonglong2*)&sm->hsm[half*128 + k][4];
        ffma2(yacc[0], h01.x, w2);
        ffma2(yacc[1], h01.y, w2);
        ffma2(yacc[2], h23.x, w2);
        ffma2(yacc[3], h23.y, w2);
    }
    if (half == 0){
        sm->red[n][0] = yacc[0]; sm->red[n][1] = yacc[1];
        sm->red[n][2] = yacc[2]; sm->red[n][3] = yacc[3];
    }
    __syncthreads();
    if (half == 1){
        float bo = bout[n];
        bool masked = (iter > g_len[b]);
        #pragma unroll
        for (int q2 = 0; q2 < 4; q2++){
            float2 u = unpack2(yacc[q2]);
            float2 v = unpack2(sm->red[n][q2]);
            float y0 = masked ? 0.f : tanhf(u.x + v.x + bo);
            float y1 = masked ? 0.f : tanhf(u.y + v.y + bo);
            g_hh[(size_t)(row0 + 2*q2    )*256 + n] = __float2half(y0);
            g_hh[(size_t)(row0 + 2*q2 + 1)*256 + n] = __float2half(y1);
        }
    }
    __syncthreads();
}

// ---------- 64x64 weight tile transpose fp32 -> [n][k] half ----------
__device__ void transpose_w(const float* __restrict__ src, __half* __restrict__ dst,
                            int Nn, int tk, int tn, char* dyn)
{
    float (*ts)[65] = (float(*)[65])dyn;
    const int t = threadIdx.x;
    const int rr = t >> 6, cc = t & 63;
    #pragma unroll
    for (int pass = 0; pass < 8; pass++){
        int r = pass*8 + rr;
        ts[r][cc] = src[(size_t)(tk*64 + r)*Nn + tn*64 + cc];
    }
    __syncthreads();
    #pragma unroll
    for (int pass = 0; pass < 8; pass++){
        int r = pass*8 + rr;
        dst[(size_t)(tn*64 + r)*256 + tk*64 + cc] = __float2half(ts[cc][r]);
    }
    __syncthreads();
}

// ---------- single persistent kernel ----------
__global__ void __launch_bounds__(512) fused_kernel(
    const int* __restrict__ tokens, const float* __restrict__ A,
    const float* __restrict__ root, const float* __restrict__ emb,
    const float* __restrict__ Wp,   const float* __restrict__ bp,
    const float* __restrict__ Win,  const float* __restrict__ bin,
    const float* __restrict__ Wout, const float* __restrict__ bout,
    float* __restrict__ out)
{
    extern __shared__ char smraw[];
    char* dyn = (char*)((((size_t)smraw) + 1023) & ~(size_t)1023);
    __shared__ float s_red[64][8][2];

    const int bid = blockIdx.x;
    const int t = threadIdx.x;
    const int b = bid >> 3, r = bid & 7;

    // prologue: gather (half), zero h, lengths, weight transposes
    {
        int idx = r*512 + t;
        int l = idx >> 6;
        int c4 = (idx & 63) * 4;
        int row = b*64 + l;
        int tok = tokens[l*16 + b];
        float4 e4 = *(const float4*)&emb[(size_t)tok*256 + c4];
        __half2 h0 = __floats2half2_rn(e4.x, e4.y);
        __half2 h1 = __floats2half2_rn(e4.z, e4.w);
        uint2 u; u.x = *(unsigned*)&h0; u.y = *(unsigned*)&h1;
        *(uint2*)&g_xh[(size_t)row*256 + c4] = u;
        uint2 z; z.x = 0u; z.y = 0u;
        *(uint2*)&g_hh[(size_t)row*256 + c4] = z;
        if (r == 0 && t == 0){
            int c = 0;
            for (int l2 = 0; l2 < 64; l2++) c += (tokens[l2*16 + b] != 0);
            g_len[b] = c;
        }
    }
    transpose_w(Wp, g_wpH, 2048, bid >> 5, bid & 31, dyn);       // 128 tiles
    if (bid < 48)
        transpose_w(Win, g_winH, 768, bid / 12, bid % 12, dyn);  // 48 tiles
    grid_sync();

    // persistent einsum A
    stage_Ae(A, b, r, dyn);

    // hoisted in_proj (blocks r<3; Win slice staged into B region temporarily)
    if (r < 3){
        stage_B(g_winH, r*256, dyn);
        gemm_mma(g_xh, bin, g_io, 768, b*64, r*256, 0, dyn, s_red);
    }
    // persistent Wp slice for the recurrence
    stage_B(g_wpH, r*256, dyn);
    group_sync(b);

    // 64-step recurrence — batch-local
    for (int it = 0; it < 64; it++){
        gemm_mma(g_hh, bp, (float*)0, 2048, b*64, r*256, 1, dyn, s_red);
        einsum_mma(b, r, dyn);
        group_sync(b);
        step23(Wout, bout, 64 - it, dyn);
        group_sync(b);
    }

    // epilogue: out[b][d] = sum_i h[b,i,d] * root[b,i]
    if (r == 0 && t < 256){
        float s = 0.f;
        #pragma unroll 8
        for (int i = 0; i < 64; i++)
            s += __half2float(g_hh[(size_t)(b*64 + i)*256 + t]) * root[b*64 + i];
        out[b*256 + t] = s;
    }
}

extern "C" void kernel_launch(void* const* d_in, const int* in_sizes, int n_in,
                              void* d_out, int out_size)
{
    const int*   tokens = (const int*)  d_in[0];
    const float* A      = (const float*)d_in[1];
    const float* root   = (const float*)d_in[2];
    const float* emb    = (const float*)d_in[3];
    const float* Wp     = (const float*)d_in[4];
    const float* bp     = (const float*)d_in[5];
    const float* Win    = (const float*)d_in[6];
    const float* bin    = (const float*)d_in[7];
    const float* Wout   = (const float*)d_in[8];
    const float* bout   = (const float*)d_in[9];

    cudaFuncSetAttribute(fused_kernel, cudaFuncAttributeMaxDynamicSharedMemorySize, SMEM_DYN);
    fused_kernel<<<NBLOCKS, 512, SMEM_DYN>>>(tokens, A, root, emb, Wp, bp, Win, bin,
                                             Wout, bout, (float*)d_out);
}

// round 14
// speedup vs baseline: 2.9161x; 1.2779x over previous
#include <cuda_runtime.h>
#include <cuda_fp16.h>

#define NBLOCKS 128
typedef unsigned long long ull;

__device__ __align__(16) __half g_xh [1024*256];     // gathered embeddings (half)
__device__ __align__(16) float  g_io [1024*768];     // shift|scale|proj_x (fp32)
__device__ __align__(16) float  g_part[16*8*64*256]; // [b][rel][j][d] partial lin_sum
__device__ __align__(16) __half g_hh [1024*256];     // recurrent state (half)
__device__ __align__(16) __half g_wpH [2048*256];    // Wp  transposed [n][k] half
__device__ __align__(16) __half g_winH[768*256];     // Win transposed [n][k] half
__device__ __align__(16) __half g_woH [256*256];     // Wout transposed [n][k] half
__device__ int g_len[16];
__device__ unsigned g_cnt = 0, g_gen = 0;
__device__ unsigned g_gcnt[16*32];
__device__ unsigned g_ggen[16*32];

// ---------- helpers ----------
__device__ __forceinline__ void cpa16(void* s, const void* g){
    unsigned ss = (unsigned)__cvta_generic_to_shared(s);
    asm volatile("cp.async.cg.shared.global [%0], [%1], 16;\n" :: "r"(ss), "l"(g));
}
#define CPA_COMMIT() asm volatile("cp.async.commit_group;\n" ::: "memory")
#define CPA_WAIT0()  asm volatile("cp.async.wait_group 0;\n" ::: "memory")
#define CPA_WAIT1()  asm volatile("cp.async.wait_group 1;\n" ::: "memory")

// legacy HMMA m16n8k16 fp16, fp32 accumulate (base sm_103-legal)
__device__ __forceinline__ void mma_f16(float* d, const unsigned* a, const unsigned* b){
    asm volatile(
        "mma.sync.aligned.m16n8k16.row.col.f32.f16.f16.f32 "
        "{%0,%1,%2,%3}, {%4,%5,%6,%7}, {%8,%9}, {%0,%1,%2,%3};"
        : "+f"(d[0]), "+f"(d[1]), "+f"(d[2]), "+f"(d[3])
        : "r"(a[0]), "r"(a[1]), "r"(a[2]), "r"(a[3]), "r"(b[0]), "r"(b[1]));
}

// ---------- dynamic smem layout (bytes) ----------
// [0,135168)        B persistent half[256 n][264 k]   (Wp slice; Win slice during in_proj)
// [135168,168960)   A tile half[64 m][264 k]  | StepSm
// [168960,205824)   P half[256 d][72 i]
// [205824,215040)   AsE half[64 j][72 i]  (persistent einsum A)
#define OFF_A    135168
#define OFF_P    168960
#define OFF_ASE  205824
#define SMEM_DYN 215040
struct StepSm { __half hsmh[16][264]; float lnp[8][2][2]; };

// ---------- barriers (tight spin) ----------
__device__ __forceinline__ void grid_sync(){
    __threadfence();
    __syncthreads();
    if (threadIdx.x == 0){
        unsigned my = *(volatile unsigned*)&g_gen;
        if (atomicAdd(&g_cnt, 1u) == NBLOCKS - 1u){
            g_cnt = 0;
            __threadfence();
            atomicAdd(&g_gen, 1u);
        } else {
            while (*(volatile unsigned*)&g_gen == my) {}
        }
        __threadfence();
    }
    __syncthreads();
}

__device__ __forceinline__ void group_sync(int b){
    __threadfence();
    __syncthreads();
    if (threadIdx.x == 0){
        volatile unsigned* gen = &g_ggen[b*32];
        unsigned my = *gen;
        if (atomicAdd(&g_gcnt[b*32], 1u) == 7u){
            g_gcnt[b*32] = 0;
            __threadfence();
            atomicAdd((unsigned*)&g_ggen[b*32], 1u);
        } else {
            while (*gen == my) {}
        }
        __threadfence();
    }
    __syncthreads();
}

// ---------- stage persistent B slice (256 n x 256 k half) into smem ----------
__device__ void stage_B(const __half* __restrict__ BsrcT, int n0, char* dyn){
    __half* Bsm = (__half*)dyn;
    const int t = threadIdx.x;
    #pragma unroll
    for (int i = 0; i < 16; i++){
        int idx = t + i*512;
        int row = idx >> 5, col8 = (idx & 31)*8;
        cpa16(Bsm + row*264 + col8, BsrcT + (size_t)(n0 + row)*256 + col8);
    }
    CPA_COMMIT(); CPA_WAIT0();
    __syncthreads();
}

// ---------- fp16 HMMA GEMM tile: 64(m) x 256(n), K=256; B persistent ----------
// A staged in 2 overlapping k-halves. mode 0: STG fp32. mode 1: LN, STS half P[d][i].
__device__ void gemm_mma(const __half* __restrict__ Asrc,
                         const float* __restrict__ bias, float* __restrict__ outp,
                         int N, int m0, int n0, int mode, char* dyn,
                         float (*s_red)[8][2])
{
    const int t = threadIdx.x, w = t >> 5, lane = t & 31;
    const int wm = w & 1, wn = w >> 1;
    const int r4 = lane >> 2, q = lane & 3;

    __half* Asm = (__half*)(dyn + OFF_A);        // [64][264]
    const __half* Bsm = (const __half*)dyn;      // [256][264] persistent

    // stage A tile in two k-halves (overlap second half with first-half MMA)
    #pragma unroll
    for (int i = 0; i < 2; i++){
        int idx = t + i*512;                  // k[0:128)
        int row = idx >> 4, col8 = (idx & 15)*8;
        cpa16(Asm + row*264 + col8, Asrc + (size_t)(m0 + row)*256 + col8);
    }
    CPA_COMMIT();
    #pragma unroll
    for (int i = 0; i < 2; i++){
        int idx = t + i*512;                  // k[128:256)
        int row = idx >> 4, col8 = (idx & 15)*8 + 128;
        cpa16(Asm + row*264 + col8, Asrc + (size_t)(m0 + row)*256 + col8);
    }
    CPA_COMMIT();

    float acc[2][4][4];
    #pragma unroll
    for (int g = 0; g < 2; g++)
        #pragma unroll
        for (int f = 0; f < 4; f++)
            #pragma unroll
            for (int rr = 0; rr < 4; rr++) acc[g][f][rr] = 0.f;

    const __half* Ab = Asm + (wm*32 + r4)*264 + 2*q;
    const __half* Bb = Bsm + (wn*32 + r4)*264 + 2*q;

    CPA_WAIT1();
    __syncthreads();
    #pragma unroll 4
    for (int ks = 0; ks < 8; ks++){
        const int kb = ks*16;
        unsigned a[2][4], bf[4][2];
        #pragma unroll
        for (int g = 0; g < 2; g++){
            const __half* Ag = Ab + g*16*264 + kb;
            a[g][0] = *(const unsigned*)(Ag);
            a[g][1] = *(const unsigned*)(Ag + 8*264);
            a[g][2] = *(const unsigned*)(Ag + 8);
            a[g][3] = *(const unsigned*)(Ag + 8*264 + 8);
        }
        #pragma unroll
        for (int f = 0; f < 4; f++){
            const __half* Bf = Bb + f*8*264 + kb;
            bf[f][0] = *(const unsigned*)(Bf);
            bf[f][1] = *(const unsigned*)(Bf + 8);
        }
        #pragma unroll
        for (int g = 0; g < 2; g++)
            #pragma unroll
            for (int f = 0; f < 4; f++)
                mma_f16(acc[g][f], a[g], bf[f]);
    }
    CPA_WAIT0();
    __syncthreads();
    #pragma unroll 4
    for (int ks = 8; ks < 16; ks++){
        const int kb = ks*16;
        unsigned a[2][4], bf[4][2];
        #pragma unroll
        for (int g = 0; g < 2; g++){
            const __half* Ag = Ab + g*16*264 + kb;
            a[g][0] = *(const unsigned*)(Ag);
            a[g][1] = *(const unsigned*)(Ag + 8*264);
            a[g][2] = *(const unsigned*)(Ag + 8);
            a[g][3] = *(const unsigned*)(Ag + 8*264 + 8);
        }
        #pragma unroll
        for (int f = 0; f < 4; f++){
            const __half* Bf = Bb + f*8*264 + kb;
            bf[f][0] = *(const unsigned*)(Bf);
            bf[f][1] = *(const unsigned*)(Bf + 8);
        }
        #pragma unroll
        for (int g = 0; g < 2; g++)
            #pragma unroll
            for (int f = 0; f < 4; f++)
                mma_f16(acc[g][f], a[g], bf[f]);
    }

    #pragma unroll
    for (int f = 0; f < 4; f++){
        float b0 = bias[n0 + wn*32 + f*8 + 2*q];
        float b1 = bias[n0 + wn*32 + f*8 + 2*q + 1];
        #pragma unroll
        for (int g = 0; g < 2; g++){
            acc[g][f][0] += b0; acc[g][f][1] += b1;
            acc[g][f][2] += b0; acc[g][f][3] += b1;
        }
    }

    if (mode == 1){
        #pragma unroll
        for (int g = 0; g < 2; g++)
            #pragma unroll
            for (int h = 0; h < 2; h++){
                float s1 = 0.f, s2 = 0.f;
                #pragma unroll
                for (int f = 0; f < 4; f++){
                    float v0 = acc[g][f][2*h], v1 = acc[g][f][2*h + 1];
                    s1 += v0 + v1; s2 += v0*v0 + v1*v1;
                }
                s1 += __shfl_xor_sync(0xffffffffu, s1, 1);
                s2 += __shfl_xor_sync(0xffffffffu, s2, 1);
                s1 += __shfl_xor_sync(0xffffffffu, s1, 2);
                s2 += __shfl_xor_sync(0xffffffffu, s2, 2);
                if (q == 0){
                    int rl = wm*32 + g*16 + h*8 + r4;
                    s_red[rl][wn][0] = s1; s_red[rl][wn][1] = s2;
                }
            }
        __syncthreads();
        __half* P = (__half*)(dyn + OFF_P);    // [256 d][72 i]
        #pragma unroll
        for (int g = 0; g < 2; g++)
            #pragma unroll
            for (int h = 0; h < 2; h++){
                int rl = wm*32 + g*16 + h*8 + r4;
                float t1 = 0.f, t2 = 0.f;
                #pragma unroll
                for (int j = 0; j < 8; j++){ t1 += s_red[rl][j][0]; t2 += s_red[rl][j][1]; }
                float mean = t1 * (1.f/256.f);
                float var  = t2 * (1.f/256.f) - mean*mean;
                float rstd = rsqrtf(var + 1e-5f);
                #pragma unroll
                for (int f = 0; f < 4; f++){
                    float v0 = (acc[g][f][2*h]   - mean) * rstd;
                    float v1 = (acc[g][f][2*h+1] - mean) * rstd;
                    int colb = wn*32 + f*8 + 2*q;
                    P[(size_t)(colb  )*72 + rl] = __float2half(v0);
                    P[(size_t)(colb+1)*72 + rl] = __float2half(v1);
                }
            }
    } else {
        #pragma unroll
        for (int g = 0; g < 2; g++)
            #pragma unroll
            for (int h = 0; h < 2; h++){
                int row = m0 + wm*32 + g*16 + h*8 + r4;
                float* op = outp + (size_t)row*N + n0 + wn*32 + 2*q;
                #pragma unroll
                for (int f = 0; f < 4; f++){
                    float2 o2; o2.x = acc[g][f][2*h]; o2.y = acc[g][f][2*h+1];
                    *(float2*)(op + f*8) = o2;
                }
            }
    }
    __syncthreads();
}

// ---------- einsum A staging (once; loop-invariant) ----------
__device__ void stage_Ae(const float* __restrict__ A, int b, int r, char* dyn){
    __half* AsE = (__half*)(dyn + OFF_ASE);   // [64 j][72 i]
    const float* Ab = A + (size_t)b*32768 + r;
    const int t = threadIdx.x;
    #pragma unroll
    for (int pass = 0; pass < 8; pass++){
        int e = pass*512 + t;
        int j = e & 63, i = e >> 6;
        AsE[j*72 + i] = __float2half(Ab[(size_t)i*512 + j*8]);
    }
    __syncthreads();
}

// ---------- einsum (fp16 HMMA): partial[j][d] = sum_i A[b,i,j,r]*p_r[i][d] ----------
__device__ void einsum_mma(int b, int r, char* dyn)
{
    const int t = threadIdx.x, w = t >> 5, lane = t & 31;
    const int wm = w & 1, wn = w >> 1;
    const int r4 = lane >> 2, q = lane & 3;

    const __half* AsE = (const __half*)(dyn + OFF_ASE);
    const __half* P   = (const __half*)(dyn + OFF_P);

    float acc[2][4][4];
    #pragma unroll
    for (int g = 0; g < 2; g++)
        #pragma unroll
        for (int f = 0; f < 4; f++)
            #pragma unroll
            for (int rr = 0; rr < 4; rr++) acc[g][f][rr] = 0.f;

    const __half* Ab = AsE + (wm*32 + r4)*72 + 2*q;
    const __half* Bb = P   + (wn*32 + r4)*72 + 2*q;
    #pragma unroll
    for (int ks = 0; ks < 4; ks++){
        const int kb = ks*16;
        unsigned a[2][4], bf[4][2];
        #pragma unroll
        for (int g = 0; g < 2; g++){
            const __half* Ag = Ab + g*16*72 + kb;
            a[g][0] = *(const unsigned*)(Ag);
            a[g][1] = *(const unsigned*)(Ag + 576);
            a[g][2] = *(const unsigned*)(Ag + 8);
            a[g][3] = *(const unsigned*)(Ag + 584);
        }
        #pragma unroll
        for (int f = 0; f < 4; f++){
            const __half* Bf = Bb + f*8*72 + kb;
            bf[f][0] = *(const unsigned*)(Bf);
            bf[f][1] = *(const unsigned*)(Bf + 8);
        }
        #pragma unroll
        for (int g = 0; g < 2; g++)
            #pragma unroll
            for (int f = 0; f < 4; f++)
                mma_f16(acc[g][f], a[g], bf[f]);
    }

    float* pb = g_part + (size_t)(b*8 + r)*64*256;
    #pragma unroll
    for (int g = 0; g < 2; g++)
        #pragma unroll
        for (int h = 0; h < 2; h++){
            int j = wm*32 + g*16 + h*8 + r4;
            float* op = pb + (size_t)j*256 + wn*32 + 2*q;
            #pragma unroll
            for (int f = 0; f < 4; f++){
                float2 o2; o2.x = acc[g][f][2*h]; o2.y = acc[g][f][2*h+1];
                *(float2*)(op + f*8) = o2;
            }
        }
    __syncthreads();
}

// ---------- step phases 2+3 ----------
__device__ void step23(const float* __restrict__ bout, int iter, char* dyn)
{
    StepSm* sm = (StepSm*)(dyn + OFF_A);
    const int t  = threadIdx.x;
    const int b  = blockIdx.x >> 3;
    const int j0 = (blockIdx.x & 7) * 8;
    const int row0 = b*64 + j0;
    const int w = t >> 5, lane = t & 31;

    // phase 2: 16 warps; warp = (row r, d-half dh); h -> hsmh[r][d] (half)
    {
        const int r  = w & 7;
        const int dh = w >> 3;
        const int j  = j0 + r;
        const float* iorow = g_io + (size_t)(row0 + r)*768;
        const float* pp = g_part + (size_t)(b*8)*64*256 + (size_t)j*256;
        float hv2[4];
        float s = 0.f, s2 = 0.f;
        #pragma unroll
        for (int qq = 0; qq < 4; qq++){
            int d = dh*128 + qq*32 + lane;
            float x = 0.f;
            #pragma unroll
            for (int rel = 0; rel < 8; rel++)
                x += pp[(size_t)rel*64*256 + d];
            x = x - tanhf(x);
            x += iorow[512 + d];
            hv2[qq] = x;
            s += x; s2 += x*x;
        }
        #pragma unroll
        for (int o = 16; o > 0; o >>= 1){
            s  += __shfl_xor_sync(0xffffffffu, s,  o);
            s2 += __shfl_xor_sync(0xffffffffu, s2, o);
        }
        if (lane == 0){ sm->lnp[r][dh][0] = s; sm->lnp[r][dh][1] = s2; }
        __syncthreads();
        float t1 = sm->lnp[r][0][0] + sm->lnp[r][1][0];
        float t2 = sm->lnp[r][0][1] + sm->lnp[r][1][1];
        float mean = t1 * (1.f/256.f);
        float var  = t2 * (1.f/256.f) - mean*mean;
        float rstd = rsqrtf(var + 1e-5f);
        #pragma unroll
        for (int qq = 0; qq < 4; qq++){
            int d = dh*128 + qq*32 + lane;
            float lnv = (hv2[qq]-mean)*rstd;
            float g = fmaf(iorow[d], lnv, iorow[256+d]);
            sm->hsmh[r][d] = __float2half(fmaxf(g, 0.f));
        }
    }
    __syncthreads();

    // phase 3: y = tanh(h @ Wout + b) via fp16 HMMA; warp w owns n16 = w*16
    {
        const __half* hs = &sm->hsmh[0][0];
        const int n16 = w * 16;
        const int m  = lane >> 2;            // row 0..7 (rows 8..15: A-frag zeroed)
        const int kq = (lane & 3) * 2;
        float acc3[2][4];
        #pragma unroll
        for (int fr = 0; fr < 2; fr++)
            #pragma unroll
            for (int rr = 0; rr < 4; rr++) acc3[fr][rr] = 0.f;

        #pragma unroll 4
        for (int ks = 0; ks < 16; ks++){
            const int kb = ks*16;
            unsigned a[4], bf[2][2];
            a[0] = *(const unsigned*)&hs[m*264 + kb + kq];
            a[2] = *(const unsigned*)&hs[m*264 + kb + kq + 8];
            a[1] = 0u; a[3] = 0u;
            #pragma unroll
            for (int fr = 0; fr < 2; fr++){
                const __half* wp = g_woH + (size_t)(n16 + fr*8 + m)*256 + kb + kq;
                bf[fr][0] = *(const unsigned*)(wp);
                bf[fr][1] = *(const unsigned*)(wp + 8);
            }
            mma_f16(acc3[0], a, bf[0]);
            mma_f16(acc3[1], a, bf[1]);
        }

        bool masked = (iter > g_len[b]);
        const int gr = row0 + m;
        #pragma unroll
        for (int fr = 0; fr < 2; fr++){
            int n = n16 + fr*8 + kq;
            float2 bo = *(const float2*)&bout[n];
            float y0 = masked ? 0.f : tanhf(acc3[fr][0] + bo.x);
            float y1 = masked ? 0.f : tanhf(acc3[fr][1] + bo.y);
            __half2 hy = __floats2half2_rn(y0, y1);
            *(unsigned*)&g_hh[(size_t)gr*256 + n] = *(unsigned*)&hy;
        }
    }
    __syncthreads();
}

// ---------- 64x64 weight tile transpose fp32 -> [n][k] half ----------
__device__ void transpose_w(const float* __restrict__ src, __half* __restrict__ dst,
                            int Nn, int tk, int tn, char* dyn)
{
    float (*ts)[65] = (float(*)[65])dyn;
    const int t = threadIdx.x;
    const int rr = t >> 6, cc = t & 63;
    #pragma unroll
    for (int pass = 0; pass < 8; pass++){
        int r = pass*8 + rr;
        ts[r][cc] = src[(size_t)(tk*64 + r)*Nn + tn*64 + cc];
    }
    __syncthreads();
    #pragma unroll
    for (int pass = 0; pass < 8; pass++){
        int r = pass*8 + rr;
        dst[(size_t)(tn*64 + r)*256 + tk*64 + cc] = __float2half(ts[cc][r]);
    }
    __syncthreads();
}

// ---------- single persistent kernel ----------
__global__ void __launch_bounds__(512) fused_kernel(
    const int* __restrict__ tokens, const float* __restrict__ A,
    const float* __restrict__ root, const float* __restrict__ emb,
    const float* __restrict__ Wp,   const float* __restrict__ bp,
    const float* __restrict__ Win,  const float* __restrict__ bin,
    const float* __restrict__ Wout, const float* __restrict__ bout,
    float* __restrict__ out)
{
    extern __shared__ char smraw[];
    char* dyn = (char*)((((size_t)smraw) + 1023) & ~(size_t)1023);
    __shared__ float s_red[64][8][2];

    const int bid = blockIdx.x;
    const int t = threadIdx.x;
    const int b = bid >> 3, r = bid & 7;

    // prologue: gather (half), zero h, lengths, weight transposes
    {
        int idx = r*512 + t;
        int l = idx >> 6;
        int c4 = (idx & 63) * 4;
        int row = b*64 + l;
        int tok = tokens[l*16 + b];
        float4 e4 = *(const float4*)&emb[(size_t)tok*256 + c4];
        __half2 h0 = __floats2half2_rn(e4.x, e4.y);
        __half2 h1 = __floats2half2_rn(e4.z, e4.w);
        uint2 u; u.x = *(unsigned*)&h0; u.y = *(unsigned*)&h1;
        *(uint2*)&g_xh[(size_t)row*256 + c4] = u;
        uint2 z; z.x = 0u; z.y = 0u;
        *(uint2*)&g_hh[(size_t)row*256 + c4] = z;
        if (r == 0 && t == 0){
            int c = 0;
            for (int l2 = 0; l2 < 64; l2++) c += (tokens[l2*16 + b] != 0);
            g_len[b] = c;
        }
    }
    transpose_w(Wp, g_wpH, 2048, bid >> 5, bid & 31, dyn);       // 128 tiles
    if (bid < 48)
        transpose_w(Win, g_winH, 768, bid / 12, bid % 12, dyn);  // 48 tiles
    if (bid < 16)
        transpose_w(Wout, g_woH, 256, bid >> 2, bid & 3, dyn);   // 16 tiles
    grid_sync();

    // persistent einsum A
    stage_Ae(A, b, r, dyn);

    // hoisted in_proj (blocks r<3; Win slice staged into B region temporarily)
    if (r < 3){
        stage_B(g_winH, r*256, dyn);
        gemm_mma(g_xh, bin, g_io, 768, b*64, r*256, 0, dyn, s_red);
    }
    // persistent Wp slice for the recurrence
    stage_B(g_wpH, r*256, dyn);
    group_sync(b);

    // 64-step recurrence — batch-local
    for (int it = 0; it < 64; it++){
        gemm_mma(g_hh, bp, (float*)0, 2048, b*64, r*256, 1, dyn, s_red);
        einsum_mma(b, r, dyn);
        group_sync(b);
        step23(bout, 64 - it, dyn);
        group_sync(b);
    }

    // epilogue: out[b][d] = sum_i h[b,i,d] * root[b,i]
    if (r == 0 && t < 256){
        float s = 0.f;
        #pragma unroll 8
        for (int i = 0; i < 64; i++)
            s += __half2float(g_hh[(size_t)(b*64 + i)*256 + t]) * root[b*64 + i];
        out[b*256 + t] = s;
    }
}

extern "C" void kernel_launch(void* const* d_in, const int* in_sizes, int n_in,
                              void* d_out, int out_size)
{
    const int*   tokens = (const int*)  d_in[0];
    const float* A      = (const float*)d_in[1];
    const float* root   = (const float*)d_in[2];
    const float* emb    = (const float*)d_in[3];
    const float* Wp     = (const float*)d_in[4];
    const float* bp     = (const float*)d_in[5];
    const float* Win    = (const float*)d_in[6];
    const float* bin    = (const float*)d_in[7];
    const float* Wout   = (const float*)d_in[8];
    const float* bout   = (const float*)d_in[9];

    cudaFuncSetAttribute(fused_kernel, cudaFuncAttributeMaxDynamicSharedMemorySize, SMEM_DYN);
    fused_kernel<<<NBLOCKS, 512, SMEM_DYN>>>(tokens, A, root, emb, Wp, bp, Win, bin,
                                             Wout, bout, (float*)d_out);
}

// round 15
// speedup vs baseline: 2.9280x; 1.0041x over previous
#include <cuda_runtime.h>
#include <cuda_fp16.h>

#define NBLOCKS 128
typedef unsigned long long ull;

__device__ __align__(16) __half g_xh [1024*256];     // gathered embeddings (half)
__device__ __align__(16) float  g_io [1024*768];     // shift|scale|proj_x (fp32)
__device__ __align__(16) float  g_part[16*8*64*256]; // [b][rel][j][d] partial lin_sum
__device__ __align__(16) __half g_hh [1024*256];     // recurrent state (half)
__device__ __align__(16) __half g_wpH [2048*256];    // Wp  transposed [n][k] half
__device__ __align__(16) __half g_winH[768*256];     // Win transposed [n][k] half
__device__ __align__(16) __half g_woH [256*256];     // Wout transposed [n][k] half
__device__ int g_len[16];
__device__ unsigned g_cnt = 0, g_gen = 0;
__device__ unsigned g_gcnt[16*32];
__device__ unsigned g_ggen[16*32];

// ---------- helpers ----------
__device__ __forceinline__ void cpa16(void* s, const void* g){
    unsigned ss = (unsigned)__cvta_generic_to_shared(s);
    asm volatile("cp.async.cg.shared.global [%0], [%1], 16;\n" :: "r"(ss), "l"(g));
}
#define CPA_COMMIT() asm volatile("cp.async.commit_group;\n" ::: "memory")
#define CPA_WAIT0()  asm volatile("cp.async.wait_group 0;\n" ::: "memory")
#define CPA_WAIT1()  asm volatile("cp.async.wait_group 1;\n" ::: "memory")

// legacy HMMA m16n8k16 fp16, fp32 accumulate (base sm_103-legal)
__device__ __forceinline__ void mma_f16(float* d, const unsigned* a, const unsigned* b){
    asm volatile(
        "mma.sync.aligned.m16n8k16.row.col.f32.f16.f16.f32 "
        "{%0,%1,%2,%3}, {%4,%5,%6,%7}, {%8,%9}, {%0,%1,%2,%3};"
        : "+f"(d[0]), "+f"(d[1]), "+f"(d[2]), "+f"(d[3])
        : "r"(a[0]), "r"(a[1]), "r"(a[2]), "r"(a[3]), "r"(b[0]), "r"(b[1]));
}

// ---------- dynamic smem layout (bytes) ----------
// [0,135168)        B persistent half[256 n][264 k]   (Wp slice; Win slice during in_proj)
// [135168,168960)   A tile half[64 m][264 k]  | StepSm
// [168960,205824)   P half[256 d][72 i]
// [205824,215040)   AsE half[64 j][72 i]  (persistent einsum A)
#define OFF_A    135168
#define OFF_P    168960
#define OFF_ASE  205824
#define SMEM_DYN 215040
struct StepSm { __half hsmh[16][264]; float lnp[8][2][2]; };

// ---------- lightweight acq/rel barriers ----------
// Entry: bar.sync (cumulative) -> thread0 releases block writes via acq_rel atomic.
// Exit: acquire spin/arrive + ONE threadfence (CCTL.IVALL: invalidates SM's L1D so
// all threads' plain LDGs see peer blocks' writes) + bar.sync.
__device__ __forceinline__ void bar_lite(unsigned* cnt, unsigned* gen, unsigned last){
    __syncthreads();
    if (threadIdx.x == 0){
        unsigned my, old;
        asm volatile("ld.relaxed.gpu.u32 %0, [%1];" : "=r"(my) : "l"(gen) : "memory");
        asm volatile("atom.add.acq_rel.gpu.u32 %0, [%1], 1;" : "=r"(old) : "l"(cnt) : "memory");
        if (old == last){
            asm volatile("st.relaxed.gpu.u32 [%0], 0;" :: "l"(cnt) : "memory");
            unsigned du;
            asm volatile("atom.add.release.gpu.u32 %0, [%1], 1;" : "=r"(du) : "l"(gen) : "memory");
        } else {
            unsigned v;
            do {
                asm volatile("ld.acquire.gpu.u32 %0, [%1];" : "=r"(v) : "l"(gen) : "memory");
            } while (v == my);
        }
        __threadfence();   // CCTL.IVALL — flush/invalidate this SM's L1D
    }
    __syncthreads();
}

__device__ __forceinline__ void grid_sync(){
    bar_lite(&g_cnt, &g_gen, NBLOCKS - 1u);
}
__device__ __forceinline__ void group_sync(int b){
    bar_lite(&g_gcnt[b*32], &g_ggen[b*32], 7u);
}

// ---------- stage persistent B slice (256 n x 256 k half) into smem ----------
__device__ void stage_B(const __half* __restrict__ BsrcT, int n0, char* dyn){
    __half* Bsm = (__half*)dyn;
    const int t = threadIdx.x;
    #pragma unroll
    for (int i = 0; i < 16; i++){
        int idx = t + i*512;
        int row = idx >> 5, col8 = (idx & 31)*8;
        cpa16(Bsm + row*264 + col8, BsrcT + (size_t)(n0 + row)*256 + col8);
    }
    CPA_COMMIT(); CPA_WAIT0();
    __syncthreads();
}

// ---------- fp16 HMMA GEMM tile: 64(m) x 256(n), K=256; B persistent ----------
// A staged in 2 overlapping k-halves. mode 0: STG fp32. mode 1: LN, STS half P[d][i].
__device__ void gemm_mma(const __half* __restrict__ Asrc,
                         const float* __restrict__ bias, float* __restrict__ outp,
                         int N, int m0, int n0, int mode, char* dyn,
                         float (*s_red)[8][2])
{
    const int t = threadIdx.x, w = t >> 5, lane = t & 31;
    const int wm = w & 1, wn = w >> 1;
    const int r4 = lane >> 2, q = lane & 3;

    __half* Asm = (__half*)(dyn + OFF_A);        // [64][264]
    const __half* Bsm = (const __half*)dyn;      // [256][264] persistent

    // stage A tile in two k-halves (overlap second half with first-half MMA)
    #pragma unroll
    for (int i = 0; i < 2; i++){
        int idx = t + i*512;                  // k[0:128)
        int row = idx >> 4, col8 = (idx & 15)*8;
        cpa16(Asm + row*264 + col8, Asrc + (size_t)(m0 + row)*256 + col8);
    }
    CPA_COMMIT();
    #pragma unroll
    for (int i = 0; i < 2; i++){
        int idx = t + i*512;                  // k[128:256)
        int row = idx >> 4, col8 = (idx & 15)*8 + 128;
        cpa16(Asm + row*264 + col8, Asrc + (size_t)(m0 + row)*256 + col8);
    }
    CPA_COMMIT();

    float acc[2][4][4];
    #pragma unroll
    for (int g = 0; g < 2; g++)
        #pragma unroll
        for (int f = 0; f < 4; f++)
            #pragma unroll
            for (int rr = 0; rr < 4; rr++) acc[g][f][rr] = 0.f;

    const __half* Ab = Asm + (wm*32 + r4)*264 + 2*q;
    const __half* Bb = Bsm + (wn*32 + r4)*264 + 2*q;

    CPA_WAIT1();
    __syncthreads();
    #pragma unroll 4
    for (int ks = 0; ks < 8; ks++){
        const int kb = ks*16;
        unsigned a[2][4], bf[4][2];
        #pragma unroll
        for (int g = 0; g < 2; g++){
            const __half* Ag = Ab + g*16*264 + kb;
            a[g][0] = *(const unsigned*)(Ag);
            a[g][1] = *(const unsigned*)(Ag + 8*264);
            a[g][2] = *(const unsigned*)(Ag + 8);
            a[g][3] = *(const unsigned*)(Ag + 8*264 + 8);
        }
        #pragma unroll
        for (int f = 0; f < 4; f++){
            const __half* Bf = Bb + f*8*264 + kb;
            bf[f][0] = *(const unsigned*)(Bf);
            bf[f][1] = *(const unsigned*)(Bf + 8);
        }
        #pragma unroll
        for (int g = 0; g < 2; g++)
            #pragma unroll
            for (int f = 0; f < 4; f++)
                mma_f16(acc[g][f], a[g], bf[f]);
    }
    CPA_WAIT0();
    __syncthreads();
    #pragma unroll 4
    for (int ks = 8; ks < 16; ks++){
        const int kb = ks*16;
        unsigned a[2][4], bf[4][2];
        #pragma unroll
        for (int g = 0; g < 2; g++){
            const __half* Ag = Ab + g*16*264 + kb;
            a[g][0] = *(const unsigned*)(Ag);
            a[g][1] = *(const unsigned*)(Ag + 8*264);
            a[g][2] = *(const unsigned*)(Ag + 8);
            a[g][3] = *(const unsigned*)(Ag + 8*264 + 8);
        }
        #pragma unroll
        for (int f = 0; f < 4; f++){
            const __half* Bf = Bb + f*8*264 + kb;
            bf[f][0] = *(const unsigned*)(Bf);
            bf[f][1] = *(const unsigned*)(Bf + 8);
        }
        #pragma unroll
        for (int g = 0; g < 2; g++)
            #pragma unroll
            for (int f = 0; f < 4; f++)
                mma_f16(acc[g][f], a[g], bf[f]);
    }

    #pragma unroll
    for (int f = 0; f < 4; f++){
        float b0 = bias[n0 + wn*32 + f*8 + 2*q];
        float b1 = bias[n0 + wn*32 + f*8 + 2*q + 1];
        #pragma unroll
        for (int g = 0; g < 2; g++){
            acc[g][f][0] += b0; acc[g][f][1] += b1;
            acc[g][f][2] += b0; acc[g][f][3] += b1;
        }
    }

    if (mode == 1){
        #pragma unroll
        for (int g = 0; g < 2; g++)
            #pragma unroll
            for (int h = 0; h < 2; h++){
                float s1 = 0.f, s2 = 0.f;
                #pragma unroll
                for (int f = 0; f < 4; f++){
                    float v0 = acc[g][f][2*h], v1 = acc[g][f][2*h + 1];
                    s1 += v0 + v1; s2 += v0*v0 + v1*v1;
                }
                s1 += __shfl_xor_sync(0xffffffffu, s1, 1);
                s2 += __shfl_xor_sync(0xffffffffu, s2, 1);
                s1 += __shfl_xor_sync(0xffffffffu, s1, 2);
                s2 += __shfl_xor_sync(0xffffffffu, s2, 2);
                if (q == 0){
                    int rl = wm*32 + g*16 + h*8 + r4;
                    s_red[rl][wn][0] = s1; s_red[rl][wn][1] = s2;
                }
            }
        __syncthreads();
        __half* P = (__half*)(dyn + OFF_P);    // [256 d][72 i]
        #pragma unroll
        for (int g = 0; g < 2; g++)
            #pragma unroll
            for (int h = 0; h < 2; h++){
                int rl = wm*32 + g*16 + h*8 + r4;
                float t1 = 0.f, t2 = 0.f;
                #pragma unroll
                for (int j = 0; j < 8; j++){ t1 += s_red[rl][j][0]; t2 += s_red[rl][j][1]; }
                float mean = t1 * (1.f/256.f);
                float var  = t2 * (1.f/256.f) - mean*mean;
                float rstd = rsqrtf(var + 1e-5f);
                #pragma unroll
                for (int f = 0; f < 4; f++){
                    float v0 = (acc[g][f][2*h]   - mean) * rstd;
                    float v1 = (acc[g][f][2*h+1] - mean) * rstd;
                    int colb = wn*32 + f*8 + 2*q;
                    P[(size_t)(colb  )*72 + rl] = __float2half(v0);
                    P[(size_t)(colb+1)*72 + rl] = __float2half(v1);
                }
            }
    } else {
        #pragma unroll
        for (int g = 0; g < 2; g++)
            #pragma unroll
            for (int h = 0; h < 2; h++){
                int row = m0 + wm*32 + g*16 + h*8 + r4;
                float* op = outp + (size_t)row*N + n0 + wn*32 + 2*q;
                #pragma unroll
                for (int f = 0; f < 4; f++){
                    float2 o2; o2.x = acc[g][f][2*h]; o2.y = acc[g][f][2*h+1];
                    *(float2*)(op + f*8) = o2;
                }
            }
    }
    __syncthreads();
}

// ---------- einsum A staging (once; loop-invariant) ----------
__device__ void stage_Ae(const float* __restrict__ A, int b, int r, char* dyn){
    __half* AsE = (__half*)(dyn + OFF_ASE);   // [64 j][72 i]
    const float* Ab = A + (size_t)b*32768 + r;
    const int t = threadIdx.x;
    #pragma unroll
    for (int pass = 0; pass < 8; pass++){
        int e = pass*512 + t;
        int j = e & 63, i = e >> 6;
        AsE[j*72 + i] = __float2half(Ab[(size_t)i*512 + j*8]);
    }
    __syncthreads();
}

// ---------- einsum (fp16 HMMA): partial[j][d] = sum_i A[b,i,j,r]*p_r[i][d] ----------
__device__ void einsum_mma(int b, int r, char* dyn)
{
    const int t = threadIdx.x, w = t >> 5, lane = t & 31;
    const int wm = w & 1, wn = w >> 1;
    const int r4 = lane >> 2, q = lane & 3;

    const __half* AsE = (const __half*)(dyn + OFF_ASE);
    const __half* P   = (const __half*)(dyn + OFF_P);

    float acc[2][4][4];
    #pragma unroll
    for (int g = 0; g < 2; g++)
        #pragma unroll
        for (int f = 0; f < 4; f++)
            #pragma unroll
            for (int rr = 0; rr < 4; rr++) acc[g][f][rr] = 0.f;

    const __half* Ab = AsE + (wm*32 + r4)*72 + 2*q;
    const __half* Bb = P   + (wn*32 + r4)*72 + 2*q;
    #pragma unroll
    for (int ks = 0; ks < 4; ks++){
        const int kb = ks*16;
        unsigned a[2][4], bf[4][2];
        #pragma unroll
        for (int g = 0; g < 2; g++){
            const __half* Ag = Ab + g*16*72 + kb;
            a[g][0] = *(const unsigned*)(Ag);
            a[g][1] = *(const unsigned*)(Ag + 576);
            a[g][2] = *(const unsigned*)(Ag + 8);
            a[g][3] = *(const unsigned*)(Ag + 584);
        }
        #pragma unroll
        for (int f = 0; f < 4; f++){
            const __half* Bf = Bb + f*8*72 + kb;
            bf[f][0] = *(const unsigned*)(Bf);
            bf[f][1] = *(const unsigned*)(Bf + 8);
        }
        #pragma unroll
        for (int g = 0; g < 2; g++)
            #pragma unroll
            for (int f = 0; f < 4; f++)
                mma_f16(acc[g][f], a[g], bf[f]);
    }

    float* pb = g_part + (size_t)(b*8 + r)*64*256;
    #pragma unroll
    for (int g = 0; g < 2; g++)
        #pragma unroll
        for (int h = 0; h < 2; h++){
            int j = wm*32 + g*16 + h*8 + r4;
            float* op = pb + (size_t)j*256 + wn*32 + 2*q;
            #pragma unroll
            for (int f = 0; f < 4; f++){
                float2 o2; o2.x = acc[g][f][2*h]; o2.y = acc[g][f][2*h+1];
                *(float2*)(op + f*8) = o2;
            }
        }
    // no trailing __syncthreads: group_sync follows immediately
}

// ---------- step phases 2+3 ----------
__device__ void step23(const float* __restrict__ bout, int iter, char* dyn)
{
    StepSm* sm = (StepSm*)(dyn + OFF_A);
    const int t  = threadIdx.x;
    const int b  = blockIdx.x >> 3;
    const int j0 = (blockIdx.x & 7) * 8;
    const int row0 = b*64 + j0;
    const int w = t >> 5, lane = t & 31;

    // phase 2: 16 warps; warp = (row r, d-half dh); h -> hsmh[r][d] (half)
    {
        const int r  = w & 7;
        const int dh = w >> 3;
        const int j  = j0 + r;
        const float* iorow = g_io + (size_t)(row0 + r)*768;
        const float* pp = g_part + (size_t)(b*8)*64*256 + (size_t)j*256;
        float hv2[4];
        float s = 0.f, s2 = 0.f;
        #pragma unroll
        for (int qq = 0; qq < 4; qq++){
            int d = dh*128 + qq*32 + lane;
            float x = 0.f;
            #pragma unroll
            for (int rel = 0; rel < 8; rel++)
                x += pp[(size_t)rel*64*256 + d];
            x = x - tanhf(x);
            x += iorow[512 + d];
            hv2[qq] = x;
            s += x; s2 += x*x;
        }
        #pragma unroll
        for (int o = 16; o > 0; o >>= 1){
            s  += __shfl_xor_sync(0xffffffffu, s,  o);
            s2 += __shfl_xor_sync(0xffffffffu, s2, o);
        }
        if (lane == 0){ sm->lnp[r][dh][0] = s; sm->lnp[r][dh][1] = s2; }
        __syncthreads();
        float t1 = sm->lnp[r][0][0] + sm->lnp[r][1][0];
        float t2 = sm->lnp[r][0][1] + sm->lnp[r][1][1];
        float mean = t1 * (1.f/256.f);
        float var  = t2 * (1.f/256.f) - mean*mean;
        float rstd = rsqrtf(var + 1e-5f);
        #pragma unroll
        for (int qq = 0; qq < 4; qq++){
            int d = dh*128 + qq*32 + lane;
            float lnv = (hv2[qq]-mean)*rstd;
            float g = fmaf(iorow[d], lnv, iorow[256+d]);
            sm->hsmh[r][d] = __float2half(fmaxf(g, 0.f));
        }
    }
    __syncthreads();

    // phase 3: y = tanh(h @ Wout + b) via fp16 HMMA; warp w owns n16 = w*16
    {
        const __half* hs = &sm->hsmh[0][0];
        const int n16 = w * 16;
        const int m  = lane >> 2;            // row 0..7 (rows 8..15: A-frag zeroed)
        const int kq = (lane & 3) * 2;
        float acc3[2][4];
        #pragma unroll
        for (int fr = 0; fr < 2; fr++)
            #pragma unroll
            for (int rr = 0; rr < 4; rr++) acc3[fr][rr] = 0.f;

        #pragma unroll 4
        for (int ks = 0; ks < 16; ks++){
            const int kb = ks*16;
            unsigned a[4], bf[2][2];
            a[0] = *(const unsigned*)&hs[m*264 + kb + kq];
            a[2] = *(const unsigned*)&hs[m*264 + kb + kq + 8];
            a[1] = 0u; a[3] = 0u;
            #pragma unroll
            for (int fr = 0; fr < 2; fr++){
                const __half* wp = g_woH + (size_t)(n16 + fr*8 + m)*256 + kb + kq;
                bf[fr][0] = *(const unsigned*)(wp);
                bf[fr][1] = *(const unsigned*)(wp + 8);
            }
            mma_f16(acc3[0], a, bf[0]);
            mma_f16(acc3[1], a, bf[1]);
        }

        bool masked = (iter > g_len[b]);
        const int gr = row0 + m;
        #pragma unroll
        for (int fr = 0; fr < 2; fr++){
            int n = n16 + fr*8 + kq;
            float2 bo = *(const float2*)&bout[n];
            float y0 = masked ? 0.f : tanhf(acc3[fr][0] + bo.x);
            float y1 = masked ? 0.f : tanhf(acc3[fr][1] + bo.y);
            __half2 hy = __floats2half2_rn(y0, y1);
            *(unsigned*)&g_hh[(size_t)gr*256 + n] = *(unsigned*)&hy;
        }
    }
    // no trailing __syncthreads: group_sync follows immediately
}

// ---------- 64x64 weight tile transpose fp32 -> [n][k] half ----------
__device__ void transpose_w(const float* __restrict__ src, __half* __restrict__ dst,
                            int Nn, int tk, int tn, char* dyn)
{
    float (*ts)[65] = (float(*)[65])dyn;
    const int t = threadIdx.x;
    const int rr = t >> 6, cc = t & 63;
    #pragma unroll
    for (int pass = 0; pass < 8; pass++){
        int r = pass*8 + rr;
        ts[r][cc] = src[(size_t)(tk*64 + r)*Nn + tn*64 + cc];
    }
    __syncthreads();
    #pragma unroll
    for (int pass = 0; pass < 8; pass++){
        int r = pass*8 + rr;
        dst[(size_t)(tn*64 + r)*256 + tk*64 + cc] = __float2half(ts[cc][r]);
    }
    __syncthreads();
}

// ---------- single persistent kernel ----------
__global__ void __launch_bounds__(512) fused_kernel(
    const int* __restrict__ tokens, const float* __restrict__ A,
    const float* __restrict__ root, const float* __restrict__ emb,
    const float* __restrict__ Wp,   const float* __restrict__ bp,
    const float* __restrict__ Win,  const float* __restrict__ bin,
    const float* __restrict__ Wout, const float* __restrict__ bout,
    float* __restrict__ out)
{
    extern __shared__ char smraw[];
    char* dyn = (char*)((((size_t)smraw) + 1023) & ~(size_t)1023);
    __shared__ float s_red[64][8][2];

    const int bid = blockIdx.x;
    const int t = threadIdx.x;
    const int b = bid >> 3, r = bid & 7;

    // prologue: gather (half), zero h, lengths, weight transposes
    {
        int idx = r*512 + t;
        int l = idx >> 6;
        int c4 = (idx & 63) * 4;
        int row = b*64 + l;
        int tok = tokens[l*16 + b];
        float4 e4 = *(const float4*)&emb[(size_t)tok*256 + c4];
        __half2 h0 = __floats2half2_rn(e4.x, e4.y);
        __half2 h1 = __floats2half2_rn(e4.z, e4.w);
        uint2 u; u.x = *(unsigned*)&h0; u.y = *(unsigned*)&h1;
        *(uint2*)&g_xh[(size_t)row*256 + c4] = u;
        uint2 z; z.x = 0u; z.y = 0u;
        *(uint2*)&g_hh[(size_t)row*256 + c4] = z;
        if (r == 0 && t == 0){
            int c = 0;
            for (int l2 = 0; l2 < 64; l2++) c += (tokens[l2*16 + b] != 0);
            g_len[b] = c;
        }
    }
    transpose_w(Wp, g_wpH, 2048, bid >> 5, bid & 31, dyn);       // 128 tiles
    if (bid < 48)
        transpose_w(Win, g_winH, 768, bid / 12, bid % 12, dyn);  // 48 tiles
    if (bid < 16)
        transpose_w(Wout, g_woH, 256, bid >> 2, bid & 3, dyn);   // 16 tiles
    grid_sync();

    // persistent einsum A
    stage_Ae(A, b, r, dyn);

    // hoisted in_proj (blocks r<3; Win slice staged into B region temporarily)
    if (r < 3){
        stage_B(g_winH, r*256, dyn);
        gemm_mma(g_xh, bin, g_io, 768, b*64, r*256, 0, dyn, s_red);
    }
    // persistent Wp slice for the recurrence
    stage_B(g_wpH, r*256, dyn);
    group_sync(b);

    // 64-step recurrence — batch-local
    for (int it = 0; it < 64; it++){
        gemm_mma(g_hh, bp, (float*)0, 2048, b*64, r*256, 1, dyn, s_red);
        einsum_mma(b, r, dyn);
        group_sync(b);
        step23(bout, 64 - it, dyn);
        group_sync(b);
    }

    // epilogue: out[b][d] = sum_i h[b,i,d] * root[b,i]
    if (r == 0 && t < 256){
        float s = 0.f;
        #pragma unroll 8
        for (int i = 0; i < 64; i++)
            s += __half2float(g_hh[(size_t)(b*64 + i)*256 + t]) * root[b*64 + i];
        out[b*256 + t] = s;
    }
}

extern "C" void kernel_launch(void* const* d_in, const int* in_sizes, int n_in,
                              void* d_out, int out_size)
{
    const int*   tokens = (const int*)  d_in[0];
    const float* A      = (const float*)d_in[1];
    const float* root   = (const float*)d_in[2];
    const float* emb    = (const float*)d_in[3];
    const float* Wp     = (const float*)d_in[4];
    const float* bp     = (const float*)d_in[5];
    const float* Win    = (const float*)d_in[6];
    const float* bin    = (const float*)d_in[7];
    const float* Wout   = (const float*)d_in[8];
    const float* bout   = (const float*)d_in[9];

    cudaFuncSetAttribute(fused_kernel, cudaFuncAttributeMaxDynamicSharedMemorySize, SMEM_DYN);
    fused_kernel<<<NBLOCKS, 512, SMEM_DYN>>>(tokens, A, root, emb, Wp, bp, Win, bin,
                                             Wout, bout, (float*)d_out);
}